// round 12
// baseline (speedup 1.0000x reference)
#include <cuda_runtime.h>
#include <cuda_fp16.h>
#include <math.h>
#include <stdint.h>

// ---------------- problem constants ----------------
#define NTOT   65536
#define KCB    2048
#define DIM    256
#define HW     4096
#define DHW    1048576

#define OFF_LOSS 0LL
#define OFF_QOUT 1LL
#define OFF_PERP 16777217LL
#define OFF_ENC  16777218LL
#define OFF_CS   150994946LL
#define OFF_EMAW 150996994LL
#define OFF_W    151521282LL

static const float DECAYF = 0.99f;
static const float OMD    = 0.01f;
static const float EPSF   = 1e-5f;

// ---------------- device scratch ----------------
__device__ __half g_Wh[KCB * DIM];      // code-major fp16 (-2w)   (1MB)
__device__ float  g_Xf[NTOT * DIM];     // token-major fp32 x      (64MB)
__device__ float  g_wnorm[KCB];
__device__ int    g_counts[KCB];
__device__ int4   g_cand4[NTOT];        // 4 exact-rescore candidates per token (1MB)
__device__ float  g_dw[KCB * DIM];
__device__ float  g_loss;

// ---------------- helpers ----------------
__device__ __forceinline__ uint32_t smem_u32(const void* p) {
    uint32_t a;
    asm("{ .reg .u64 t; cvta.to.shared.u64 t, %1; cvt.u32.u64 %0, t; }" : "=r"(a) : "l"(p));
    return a;
}
__device__ __forceinline__ uint32_t h2u(__half2 h) {
    union { __half2 h; uint32_t u; } c; c.h = h; return c.u;
}
__device__ __forceinline__ void cp16(uint32_t dst, const void* src) {
    asm volatile("cp.async.cg.shared.global [%0], [%1], 16;" :: "r"(dst), "l"(src) : "memory");
}
__device__ __forceinline__ void cp_commit() { asm volatile("cp.async.commit_group;" ::: "memory"); }

__device__ __forceinline__ void ldm4(uint32_t a, uint32_t r[4]) {
    asm volatile("ldmatrix.sync.aligned.m8n8.x4.shared.b16 {%0,%1,%2,%3}, [%4];"
                 : "=r"(r[0]), "=r"(r[1]), "=r"(r[2]), "=r"(r[3]) : "r"(a));
}
// fp16-accumulate HMMA
__device__ __forceinline__ void mma16816h(uint32_t c[2], const uint32_t a[4],
                                          uint32_t b0, uint32_t b1) {
    asm volatile("mma.sync.aligned.m16n8k16.row.col.f16.f16.f16.f16 "
                 "{%0,%1},{%2,%3,%4,%5},{%6,%7},{%0,%1};"
                 : "+r"(c[0]), "+r"(c[1])
                 : "r"(a[0]), "r"(a[1]), "r"(a[2]), "r"(a[3]), "r"(b0), "r"(b1));
}

// ---------------- codebook prep: fp16(-2w) + norms + init ----------------
__global__ void k_prep_w(const float* __restrict__ weight) {
    int warp = threadIdx.x >> 5, lane = threadIdx.x & 31;
    int k = blockIdx.x * 8 + warp;               // 256 blocks
    float s = 0.0f;
    #pragma unroll
    for (int i = 0; i < 8; ++i) {
        int d = lane + i * 32;
        float v = weight[(size_t)k * DIM + d];
        g_Wh[(size_t)k * DIM + d] = __float2half(-2.0f * v);
        s += v * v;
    }
    #pragma unroll
    for (int o = 16; o > 0; o >>= 1) s += __shfl_down_sync(0xffffffffu, s, o);
    if (lane == 0) {
        g_wnorm[k] = s;
        g_counts[k] = 0;
        if (k == 0) g_loss = 0.0f;
    }
}

// ---------------- x prep: transpose to token-major fp32; zero dw ----------------
__global__ void k_prep_x(const float* __restrict__ z) {
    extern __shared__ float xs[];             // 64*260
    const int tid = threadIdx.x;
    // zero g_dw (1024 blocks x 512 elems)
    g_dw[(size_t)blockIdx.x * 512 + tid] = 0.0f;
    g_dw[(size_t)blockIdx.x * 512 + 256 + tid] = 0.0f;

    const int n0 = blockIdx.x * 64;
    const int b = n0 >> 12, sp0 = n0 & 4095;
    const float* zb = z + (size_t)b * DHW + sp0;
    #pragma unroll
    for (int p = 0; p < 16; ++p) {
        int lin = tid + p * 256;
        int q = lin & 63, dq4 = lin >> 6;
        float4 v;
        v.x = zb[(dq4 * 4 + 0) * HW + q];
        v.y = zb[(dq4 * 4 + 1) * HW + q];
        v.z = zb[(dq4 * 4 + 2) * HW + q];
        v.w = zb[(dq4 * 4 + 3) * HW + q];
        *(float4*)(xs + q * 260 + dq4 * 4) = v;
    }
    __syncthreads();
    #pragma unroll
    for (int p = 0; p < 16; ++p) {
        int lin = tid + p * 256;                 // 4096 = 64 q x 64 d4
        int q = lin >> 6, d4 = (lin & 63) * 4;
        *(float4*)(g_Xf + (size_t)(n0 + q) * DIM + d4) = *(float4*)(xs + q * 260 + d4);
    }
}

// ---------------- HMMA argmin GEMM (fp16 accum) + enc zero-fill ----------------
// 512 CTAs x 256 thr (8 warps: 2m x 4n, warp tile 64x32). CTA = 128 tokens x
// 2048 codes, K=256. A converted fp32->fp16 in prologue (64KB smem);
// B double-buffered (2x64KB) cp.async. Per-thread top-3 over 8 token slots;
// 48 candidates per token merged to top-4.
#define SA  0
#define SB0 65536
#define SB1 131072
#define SMT 196608

__global__ void __launch_bounds__(256, 1)
k_gemm(float* __restrict__ out) {
    extern __shared__ char sm[];
    const uint32_t sb = smem_u32(sm);
    const int tid = threadIdx.x;
    const int lane = tid & 31, warp = tid >> 5;
    const int wm = warp & 1, wn = warp >> 1;      // 2m x 4n
    const int n0 = blockIdx.x * 128;
    float2* enc2 = (float2*)(out + OFF_ENC) + (size_t)blockIdx.x * 131072;

    // B tile 0
    #pragma unroll
    for (int i = 0; i < 16; ++i) {
        int idx = tid + i * 256;
        int row = idx >> 5, ch = idx & 31;
        cp16(sb + SB0 + row * 512 + ((ch ^ (row & 7)) << 4),
             g_Wh + (size_t)row * DIM + ch * 8);
    }
    cp_commit();
    // B tile 1
    #pragma unroll
    for (int i = 0; i < 16; ++i) {
        int idx = tid + i * 256;
        int row = idx >> 5, ch = idx & 31;
        cp16(sb + SB1 + row * 512 + ((ch ^ (row & 7)) << 4),
             g_Wh + (size_t)(128 + row) * DIM + ch * 8);
    }
    cp_commit();

    // A tile: load fp32, convert to fp16, STS swizzled (overlaps B cp.async)
    #pragma unroll
    for (int i = 0; i < 16; ++i) {
        int idx = tid + i * 256;                 // 4096 chunks of 16B
        int row = idx >> 5, ch = idx & 31;
        const float* src = g_Xf + (size_t)(n0 + row) * DIM + ch * 8;
        float4 f0 = *(const float4*)src;
        float4 f1 = *(const float4*)(src + 4);
        uint4 v;
        v.x = h2u(__floats2half2_rn(f0.x, f0.y));
        v.y = h2u(__floats2half2_rn(f0.z, f0.w));
        v.z = h2u(__floats2half2_rn(f1.x, f1.y));
        v.w = h2u(__floats2half2_rn(f1.z, f1.w));
        *(uint4*)(sm + SA + row * 512 + ((ch ^ (row & 7)) << 4)) = v;
    }
    __syncthreads();

    // per-thread top-3 for 8 owned token slots (r = mi*2 + h)
    float v1[8], v2[8], v3[8];
    int   i1[8], i2[8], i3[8];
    #pragma unroll
    for (int r = 0; r < 8; ++r) {
        v1[r] = 3.4e38f; v2[r] = 3.4e38f; v3[r] = 3.4e38f;
        i1[r] = 0; i2[r] = 0; i3[r] = 0;
    }

    const float2 zz = make_float2(0.f, 0.f);

    for (int nt = 0; nt < 16; ++nt) {
        if (nt < 15) asm volatile("cp.async.wait_group 1;" ::: "memory");
        else         asm volatile("cp.async.wait_group 0;" ::: "memory");
        __syncthreads();
        const uint32_t BB = sb + ((nt & 1) ? SB1 : SB0);

        uint32_t c[4][4][2];
        #pragma unroll
        for (int mi = 0; mi < 4; ++mi)
            #pragma unroll
            for (int ni = 0; ni < 4; ++ni) { c[mi][ni][0] = 0u; c[mi][ni][1] = 0u; }

        #pragma unroll
        for (int ks = 0; ks < 16; ++ks) {
            uint32_t a[4][4];
            #pragma unroll
            for (int mi = 0; mi < 4; ++mi) {
                int row = wm * 64 + mi * 16 + (lane & 15);
                int ch = ks * 2 + (lane >> 4);
                ldm4(sb + SA + row * 512 + ((ch ^ (row & 7)) << 4), a[mi]);
            }
            // B: non-trans ldmatrix on code-major smem; two 16-code groups.
            uint32_t b0[4], b1[4];
            {
                int code = wn * 32 + ((lane & 16) >> 1) + (lane & 7);
                int ch = ks * 2 + ((lane >> 3) & 1);
                ldm4(BB + code * 512 + ((ch ^ (code & 7)) << 4), b0);
                code += 16;
                ldm4(BB + code * 512 + ((ch ^ (code & 7)) << 4), b1);
            }
            #pragma unroll
            for (int mi = 0; mi < 4; ++mi) {
                mma16816h(c[mi][0], a[mi], b0[0], b0[1]);
                mma16816h(c[mi][1], a[mi], b0[2], b0[3]);
                mma16816h(c[mi][2], a[mi], b1[0], b1[1]);
                mma16816h(c[mi][3], a[mi], b1[2], b1[3]);
            }
        }

        // zero 32 float2 chunks of this CTA's encodings slice (streaming)
        #pragma unroll
        for (int j = 0; j < 32; ++j)
            __stcs(enc2 + (size_t)(nt * 32 + j) * 256 + tid, zz);

        // fold: score = wnorm + acc  (acc = x . (-2w), fp16 pair); top-3 insert
        #pragma unroll
        for (int ni = 0; ni < 4; ++ni) {
            int col = nt * 128 + wn * 32 + ni * 8 + (lane & 3) * 2;
            float2 wn2 = *(const float2*)&g_wnorm[col];
            #pragma unroll
            for (int mi = 0; mi < 4; ++mi) {
                #pragma unroll
                for (int h = 0; h < 2; ++h) {
                    int r = mi * 2 + h;
                    float2 cf = __half22float2(*(__half2*)&c[mi][ni][h]);
                    float s0 = wn2.x + cf.x;
                    float s1 = wn2.y + cf.y;
                    if (s0 < v3[r]) {
                        if (s0 < v1[r]) { v3[r]=v2[r]; i3[r]=i2[r]; v2[r]=v1[r]; i2[r]=i1[r]; v1[r]=s0; i1[r]=col; }
                        else if (s0 < v2[r]) { v3[r]=v2[r]; i3[r]=i2[r]; v2[r]=s0; i2[r]=col; }
                        else { v3[r]=s0; i3[r]=col; }
                    }
                    if (s1 < v3[r]) {
                        if (s1 < v1[r]) { v3[r]=v2[r]; i3[r]=i2[r]; v2[r]=v1[r]; i2[r]=i1[r]; v1[r]=s1; i1[r]=col+1; }
                        else if (s1 < v2[r]) { v3[r]=v2[r]; i3[r]=i2[r]; v2[r]=s1; i2[r]=col+1; }
                        else { v3[r]=s1; i3[r]=col+1; }
                    }
                }
            }
        }

        __syncthreads();
        if (nt + 2 < 16) {
            const uint32_t NB = sb + ((nt & 1) ? SB1 : SB0);
            #pragma unroll
            for (int i = 0; i < 16; ++i) {
                int idx = tid + i * 256;
                int row = idx >> 5, ch = idx & 31;
                cp16(NB + row * 512 + ((ch ^ (row & 7)) << 4),
                     g_Wh + (size_t)((nt + 2) * 128 + row) * DIM + ch * 8);
            }
            cp_commit();
        }
    }

    // ---- per-token merge: 16 slots x top-3 -> global top-4 (smem, stride 49) ----
    __syncthreads();
    float* cv = (float*)sm;                      // 128 * 49 floats (25088 B)
    int*   ci = (int*)(sm + 25088);              // 128 * 49 ints
    const int slot = wn * 4 + (lane & 3);        // 0..15
    #pragma unroll
    for (int mi = 0; mi < 4; ++mi)
        #pragma unroll
        for (int h = 0; h < 2; ++h) {
            int r = mi * 2 + h;
            int tloc = wm * 64 + mi * 16 + h * 8 + (lane >> 2);
            cv[tloc * 49 + slot * 3 + 0] = v1[r];  ci[tloc * 49 + slot * 3 + 0] = i1[r];
            cv[tloc * 49 + slot * 3 + 1] = v2[r];  ci[tloc * 49 + slot * 3 + 1] = i2[r];
            cv[tloc * 49 + slot * 3 + 2] = v3[r];  ci[tloc * 49 + slot * 3 + 2] = i3[r];
        }
    __syncthreads();
    if (tid < 128) {
        float bv0 = 3.4e38f, bv1b = 3.4e38f, bv2b = 3.4e38f, bv3 = 3.4e38f;
        int   bx0 = 0, bx1 = 0, bx2 = 0, bx3 = 0;
        #pragma unroll
        for (int e = 0; e < 48; ++e) {
            float v = cv[tid * 49 + e];
            int   ix = ci[tid * 49 + e];
            if (v < bv3) {
                if (v < bv0) { bv3=bv2b; bx3=bx2; bv2b=bv1b; bx2=bx1; bv1b=bv0; bx1=bx0; bv0=v; bx0=ix; }
                else if (v < bv1b) { bv3=bv2b; bx3=bx2; bv2b=bv1b; bx2=bx1; bv1b=v; bx1=ix; }
                else if (v < bv2b) { bv3=bv2b; bx3=bx2; bv2b=v; bx2=ix; }
                else { bv3=v; bx3=ix; }
            }
        }
        g_cand4[n0 + tid] = make_int4(bx0, bx1, bx2, bx3);
    }
}

// ---------------- fused: exact rescore + loss + dw + encodings + q_out ----------------
// 1024 blocks (one per 64-token row) x 512 thr. Warp w owns tokens w*4..w*4+3.
__global__ void __launch_bounds__(512)
k_resq(const float* __restrict__ weight, float* __restrict__ out) {
    __shared__ float wrow[64 * 67];
    __shared__ int   idx_s[64];
    __shared__ float ls[16];
    const int tid = threadIdx.x;
    const int warp = tid >> 5, lane = tid & 31;
    const int blk = blockIdx.x;
    const int b = blk >> 6, h = blk & 63;
    const int n0 = b * HW + h * 64;

    float lacc = 0.0f;
    #pragma unroll
    for (int it = 0; it < 4; ++it) {
        int tok = n0 + warp * 4 + it;
        int4 cc = g_cand4[tok];
        const float* w0 = weight + (size_t)cc.x * DIM + lane;
        const float* w1 = weight + (size_t)cc.y * DIM + lane;
        const float* w2 = weight + (size_t)cc.z * DIM + lane;
        const float* w3 = weight + (size_t)cc.w * DIM + lane;
        float xv[8];
        float xn = 0.0f;
        float d0 = 0.0f, d1 = 0.0f, d2 = 0.0f, d3 = 0.0f;
        #pragma unroll
        for (int i = 0; i < 8; ++i) {
            xv[i] = g_Xf[(size_t)tok * DIM + lane + 32 * i];
            xn += xv[i] * xv[i];
        }
        #pragma unroll
        for (int i = 0; i < 8; ++i) {
            float a0 = __ldg(w0 + 32 * i);
            float a1 = __ldg(w1 + 32 * i);
            float a2 = __ldg(w2 + 32 * i);
            float a3 = __ldg(w3 + 32 * i);
            d0 += xv[i] * a0;
            d1 += xv[i] * a1;
            d2 += xv[i] * a2;
            d3 += xv[i] * a3;
        }
        #pragma unroll
        for (int o = 16; o > 0; o >>= 1) {
            xn += __shfl_xor_sync(0xffffffffu, xn, o);
            d0 += __shfl_xor_sync(0xffffffffu, d0, o);
            d1 += __shfl_xor_sync(0xffffffffu, d1, o);
            d2 += __shfl_xor_sync(0xffffffffu, d2, o);
            d3 += __shfl_xor_sync(0xffffffffu, d3, o);
        }
        float s0 = g_wnorm[cc.x] - 2.0f * d0;
        float s1 = g_wnorm[cc.y] - 2.0f * d1;
        float s2 = g_wnorm[cc.z] - 2.0f * d2;
        float s3 = g_wnorm[cc.w] - 2.0f * d3;
        float bs = s0; int bi = cc.x;
        if (s1 < bs || (s1 == bs && cc.y < bi)) { bs = s1; bi = cc.y; }
        if (s2 < bs || (s2 == bs && cc.z < bi)) { bs = s2; bi = cc.z; }
        if (s3 < bs || (s3 == bs && cc.w < bi)) { bs = s3; bi = cc.w; }
        // dw accumulation (coalesced REDs)
        float* dwr = g_dw + (size_t)bi * DIM + lane;
        #pragma unroll
        for (int i = 0; i < 8; ++i)
            atomicAdd(dwr + 32 * i, xv[i]);
        if (lane == 0) {
            idx_s[warp * 4 + it] = bi;
            atomicAdd(&g_counts[bi], 1);
            out[OFF_ENC + (long long)tok * KCB + bi] = 1.0f;
            lacc += bs + xn;          // == ||x - w||^2
        }
    }
    if (lane == 0) ls[warp] = lacc;
    __syncthreads();
    if (tid == 0) {
        float s = 0.0f;
        #pragma unroll
        for (int w = 0; w < 16; ++w) s += ls[w];
        atomicAdd(&g_loss, s);
    }

    // ---- quant phase: stage gathered rows, write q_out coalesced ----
    const int w = tid & 63, dg = tid >> 6;       // dg 0..7
    float* qbp = out + OFF_QOUT + (size_t)b * DHW + h * 64 + w;
    for (int c = 0; c < 4; ++c) {
        #pragma unroll
        for (int p = 0; p < 8; ++p) {
            int idx = tid + p * 512;
            int r = idx >> 6, d = idx & 63;
            wrow[r * 67 + d] = __ldg(weight + (size_t)idx_s[r] * DIM + c * 64 + d);
        }
        __syncthreads();
        #pragma unroll
        for (int s = 0; s < 8; ++s) {
            int dl = dg * 8 + s;
            int d = c * 64 + dl;
            __stcs(qbp + (size_t)d * HW, wrow[w * 67 + dl]);
        }
        __syncthreads();
    }
}

// ---------------- stats ----------------
__global__ void k_stats(const float* __restrict__ ecs, float* __restrict__ out) {
    __shared__ float sn[1024];
    __shared__ float sh[1024];
    int t = threadIdx.x;
    float c0 = (float)g_counts[t];
    float c1 = (float)g_counts[t + 1024];
    float cs0 = ecs[t] * DECAYF + OMD * c0;
    float cs1 = ecs[t + 1024] * DECAYF + OMD * c1;
    float p0 = c0 / 65536.0f, p1 = c1 / 65536.0f;
    sn[t] = cs0 + cs1;
    sh[t] = p0 * logf(p0 + 1e-10f) + p1 * logf(p1 + 1e-10f);
    __syncthreads();
    #pragma unroll
    for (int st = 512; st > 0; st >>= 1) {
        if (t < st) { sn[t] += sn[t + st]; sh[t] += sh[t + st]; }
        __syncthreads();
    }
    float n = sn[0];
    float denom = n + (float)KCB * EPSF;
    out[OFF_CS + t]        = (cs0 + EPSF) / denom * n;
    out[OFF_CS + t + 1024] = (cs1 + EPSF) / denom * n;
    if (t == 0) {
        out[OFF_PERP] = expf(-sh[0]);
        out[OFF_LOSS] = 0.25f * g_loss / 16777216.0f;
    }
}

// ---------------- EMA update ----------------
__global__ void k_ema(const float* __restrict__ emaw, float* __restrict__ out) {
    int i = blockIdx.x * 256 + threadIdx.x;
    float e = emaw[i] * DECAYF + OMD * g_dw[i];
    out[OFF_EMAW + i] = e;
    out[OFF_W + i]    = e / out[OFF_CS + (i >> 8)];
}

// ---------------- launch ----------------
extern "C" void kernel_launch(void* const* d_in, const int* in_sizes, int n_in,
                              void* d_out, int out_size) {
    const float* z    = (const float*)d_in[0];
    const float* wgt  = (const float*)d_in[1];
    const float* ecs  = (const float*)d_in[2];
    const float* emaw = (const float*)d_in[3];
    float* out = (float*)d_out;

    cudaFuncSetAttribute(k_gemm,   cudaFuncAttributeMaxDynamicSharedMemorySize, SMT);
    cudaFuncSetAttribute(k_prep_x, cudaFuncAttributeMaxDynamicSharedMemorySize, 64 * 260 * 4);

    k_prep_w <<<256, 256>>>(wgt);
    k_prep_x <<<1024, 256, 64 * 260 * 4>>>(z);
    k_gemm   <<<512, 256, SMT>>>(out);
    k_resq   <<<1024, 512>>>(wgt, out);
    k_stats  <<<1, 1024>>>(ecs, out);
    k_ema    <<<2048, 256>>>(emaw, out);
}

// round 13
// speedup vs baseline: 1.0906x; 1.0906x over previous
#include <cuda_runtime.h>
#include <cuda_fp16.h>
#include <math.h>
#include <stdint.h>

// ---------------- problem constants ----------------
#define NTOT   65536
#define KCB    2048
#define DIM    256
#define HW     4096
#define DHW    1048576

#define OFF_LOSS 0LL
#define OFF_QOUT 1LL
#define OFF_PERP 16777217LL
#define OFF_ENC  16777218LL
#define OFF_CS   150994946LL
#define OFF_EMAW 150996994LL
#define OFF_W    151521282LL

static const float DECAYF = 0.99f;
static const float OMD    = 0.01f;
static const float EPSF   = 1e-5f;

// ---------------- device scratch ----------------
__device__ __half g_Wh[KCB * DIM];      // code-major fp16 (-2w)   (1MB)
__device__ float  g_Xf[NTOT * DIM];     // token-major fp32 x      (64MB)
__device__ float  g_wnorm[KCB];
__device__ int    g_counts[KCB];
__device__ int4   g_cand4[NTOT];        // 4 exact-rescore candidates per token (1MB)
__device__ float  g_dw[KCB * DIM];
__device__ float  g_loss;

// ---------------- helpers ----------------
__device__ __forceinline__ uint32_t smem_u32(const void* p) {
    uint32_t a;
    asm("{ .reg .u64 t; cvta.to.shared.u64 t, %1; cvt.u32.u64 %0, t; }" : "=r"(a) : "l"(p));
    return a;
}
__device__ __forceinline__ uint32_t h2u(__half2 h) {
    union { __half2 h; uint32_t u; } c; c.h = h; return c.u;
}
__device__ __forceinline__ void cp16(uint32_t dst, const void* src) {
    asm volatile("cp.async.cg.shared.global [%0], [%1], 16;" :: "r"(dst), "l"(src) : "memory");
}
__device__ __forceinline__ void cp_commit() { asm volatile("cp.async.commit_group;" ::: "memory"); }

__device__ __forceinline__ void ldm4(uint32_t a, uint32_t r[4]) {
    asm volatile("ldmatrix.sync.aligned.m8n8.x4.shared.b16 {%0,%1,%2,%3}, [%4];"
                 : "=r"(r[0]), "=r"(r[1]), "=r"(r[2]), "=r"(r[3]) : "r"(a));
}
// fp16-accumulate HMMA
__device__ __forceinline__ void mma16816h(uint32_t c[2], const uint32_t a[4],
                                          uint32_t b0, uint32_t b1) {
    asm volatile("mma.sync.aligned.m16n8k16.row.col.f16.f16.f16.f16 "
                 "{%0,%1},{%2,%3,%4,%5},{%6,%7},{%0,%1};"
                 : "+r"(c[0]), "+r"(c[1])
                 : "r"(a[0]), "r"(a[1]), "r"(a[2]), "r"(a[3]), "r"(b0), "r"(b1));
}

// ---------------- codebook prep: fp16(-2w) + norms + init ----------------
__global__ void k_prep_w(const float* __restrict__ weight) {
    int warp = threadIdx.x >> 5, lane = threadIdx.x & 31;
    int k = blockIdx.x * 8 + warp;               // 256 blocks
    float s = 0.0f;
    #pragma unroll
    for (int i = 0; i < 8; ++i) {
        int d = lane + i * 32;
        float v = weight[(size_t)k * DIM + d];
        g_Wh[(size_t)k * DIM + d] = __float2half(-2.0f * v);
        s += v * v;
    }
    #pragma unroll
    for (int o = 16; o > 0; o >>= 1) s += __shfl_down_sync(0xffffffffu, s, o);
    if (lane == 0) {
        g_wnorm[k] = s;
        g_counts[k] = 0;
        if (k == 0) g_loss = 0.0f;
    }
}

// ---------------- x prep: transpose to token-major fp32; zero dw ----------------
__global__ void k_prep_x(const float* __restrict__ z) {
    extern __shared__ float xs[];             // 64*260
    const int tid = threadIdx.x;
    // zero g_dw (1024 blocks x 512 elems)
    g_dw[(size_t)blockIdx.x * 512 + tid] = 0.0f;
    g_dw[(size_t)blockIdx.x * 512 + 256 + tid] = 0.0f;

    const int n0 = blockIdx.x * 64;
    const int b = n0 >> 12, sp0 = n0 & 4095;
    const float* zb = z + (size_t)b * DHW + sp0;
    #pragma unroll
    for (int p = 0; p < 16; ++p) {
        int lin = tid + p * 256;
        int q = lin & 63, dq4 = lin >> 6;
        float4 v;
        v.x = zb[(dq4 * 4 + 0) * HW + q];
        v.y = zb[(dq4 * 4 + 1) * HW + q];
        v.z = zb[(dq4 * 4 + 2) * HW + q];
        v.w = zb[(dq4 * 4 + 3) * HW + q];
        *(float4*)(xs + q * 260 + dq4 * 4) = v;
    }
    __syncthreads();
    #pragma unroll
    for (int p = 0; p < 16; ++p) {
        int lin = tid + p * 256;                 // 4096 = 64 q x 64 d4
        int q = lin >> 6, d4 = (lin & 63) * 4;
        *(float4*)(g_Xf + (size_t)(n0 + q) * DIM + d4) = *(float4*)(xs + q * 260 + d4);
    }
}

// ---------------- HMMA argmin GEMM (fp16 accum) + enc zero-fill ----------------
// 512 CTAs x 512 thr (16 warps: 4m x 4n, warp tile 32x32). CTA = 128 tokens x
// 2048 codes, K=256. A loaded fp32 -> converted fp16 in prologue (64KB smem);
// B double-buffered (2x64KB) cp.async. Per-thread top-3; 48 cands -> top-4.
#define SA  0
#define SB0 65536
#define SB1 131072
#define SMT 196608

__global__ void __launch_bounds__(512, 1)
k_gemm(float* __restrict__ out) {
    extern __shared__ char sm[];
    const uint32_t sb = smem_u32(sm);
    const int tid = threadIdx.x;
    const int lane = tid & 31, warp = tid >> 5;
    const int wm = warp & 3, wn = warp >> 2;      // 4m x 4n
    const int n0 = blockIdx.x * 128;
    float2* enc2 = (float2*)(out + OFF_ENC) + (size_t)blockIdx.x * 131072;

    // B tile 0
    #pragma unroll
    for (int i = 0; i < 8; ++i) {
        int idx = tid + i * 512;
        int row = idx >> 5, ch = idx & 31;
        cp16(sb + SB0 + row * 512 + ((ch ^ (row & 7)) << 4),
             g_Wh + (size_t)row * DIM + ch * 8);
    }
    cp_commit();
    // B tile 1
    #pragma unroll
    for (int i = 0; i < 8; ++i) {
        int idx = tid + i * 512;
        int row = idx >> 5, ch = idx & 31;
        cp16(sb + SB1 + row * 512 + ((ch ^ (row & 7)) << 4),
             g_Wh + (size_t)(128 + row) * DIM + ch * 8);
    }
    cp_commit();

    // A tile: load fp32, convert to fp16, STS swizzled (overlaps B cp.async)
    #pragma unroll
    for (int i = 0; i < 8; ++i) {
        int idx = tid + i * 512;                 // 4096 chunks of 16B
        int row = idx >> 5, ch = idx & 31;
        const float* src = g_Xf + (size_t)(n0 + row) * DIM + ch * 8;
        float4 f0 = *(const float4*)src;
        float4 f1 = *(const float4*)(src + 4);
        uint4 v;
        v.x = h2u(__floats2half2_rn(f0.x, f0.y));
        v.y = h2u(__floats2half2_rn(f0.z, f0.w));
        v.z = h2u(__floats2half2_rn(f1.x, f1.y));
        v.w = h2u(__floats2half2_rn(f1.z, f1.w));
        *(uint4*)(sm + SA + row * 512 + ((ch ^ (row & 7)) << 4)) = v;
    }
    __syncthreads();

    // per-thread top-3 for 4 owned token slots (r = mi*2 + h)
    float v1[4], v2[4], v3[4];
    int   i1[4], i2[4], i3[4];
    #pragma unroll
    for (int r = 0; r < 4; ++r) {
        v1[r] = 3.4e38f; v2[r] = 3.4e38f; v3[r] = 3.4e38f;
        i1[r] = 0; i2[r] = 0; i3[r] = 0;
    }

    const float2 zz = make_float2(0.f, 0.f);

    for (int nt = 0; nt < 16; ++nt) {
        if (nt < 15) asm volatile("cp.async.wait_group 1;" ::: "memory");
        else         asm volatile("cp.async.wait_group 0;" ::: "memory");
        __syncthreads();
        const uint32_t BB = sb + ((nt & 1) ? SB1 : SB0);

        uint32_t c[2][4][2];
        #pragma unroll
        for (int mi = 0; mi < 2; ++mi)
            #pragma unroll
            for (int ni = 0; ni < 4; ++ni) { c[mi][ni][0] = 0u; c[mi][ni][1] = 0u; }

        #pragma unroll
        for (int ks = 0; ks < 16; ++ks) {
            uint32_t a[2][4];
            #pragma unroll
            for (int mi = 0; mi < 2; ++mi) {
                int row = wm * 32 + mi * 16 + (lane & 15);
                int ch = ks * 2 + (lane >> 4);
                ldm4(sb + SA + row * 512 + ((ch ^ (row & 7)) << 4), a[mi]);
            }
            // B: non-trans ldmatrix on code-major smem; two 16-code groups.
            uint32_t b0[4], b1[4];
            {
                int code = wn * 32 + ((lane & 16) >> 1) + (lane & 7);
                int ch = ks * 2 + ((lane >> 3) & 1);
                ldm4(BB + code * 512 + ((ch ^ (code & 7)) << 4), b0);
                code += 16;
                ldm4(BB + code * 512 + ((ch ^ (code & 7)) << 4), b1);
            }
            #pragma unroll
            for (int mi = 0; mi < 2; ++mi) {
                mma16816h(c[mi][0], a[mi], b0[0], b0[1]);
                mma16816h(c[mi][1], a[mi], b0[2], b0[3]);
                mma16816h(c[mi][2], a[mi], b1[0], b1[1]);
                mma16816h(c[mi][3], a[mi], b1[2], b1[3]);
            }
        }

        // zero 16 float2 chunks of this CTA's encodings slice (streaming)
        #pragma unroll
        for (int j = 0; j < 16; ++j)
            __stcs(enc2 + (size_t)(nt * 16 + j) * 512 + tid, zz);

        // fold: score = wnorm + acc  (acc = x . (-2w), fp16 pair); top-3 insert
        #pragma unroll
        for (int ni = 0; ni < 4; ++ni) {
            int col = nt * 128 + wn * 32 + ni * 8 + (lane & 3) * 2;
            float2 wn2 = *(const float2*)&g_wnorm[col];
            #pragma unroll
            for (int mi = 0; mi < 2; ++mi) {
                #pragma unroll
                for (int h = 0; h < 2; ++h) {
                    int r = mi * 2 + h;
                    float2 cf = __half22float2(*(__half2*)&c[mi][ni][h]);
                    float s0 = wn2.x + cf.x;
                    float s1 = wn2.y + cf.y;
                    if (s0 < v3[r]) {
                        if (s0 < v1[r]) { v3[r]=v2[r]; i3[r]=i2[r]; v2[r]=v1[r]; i2[r]=i1[r]; v1[r]=s0; i1[r]=col; }
                        else if (s0 < v2[r]) { v3[r]=v2[r]; i3[r]=i2[r]; v2[r]=s0; i2[r]=col; }
                        else { v3[r]=s0; i3[r]=col; }
                    }
                    if (s1 < v3[r]) {
                        if (s1 < v1[r]) { v3[r]=v2[r]; i3[r]=i2[r]; v2[r]=v1[r]; i2[r]=i1[r]; v1[r]=s1; i1[r]=col+1; }
                        else if (s1 < v2[r]) { v3[r]=v2[r]; i3[r]=i2[r]; v2[r]=s1; i2[r]=col+1; }
                        else { v3[r]=s1; i3[r]=col+1; }
                    }
                }
            }
        }

        __syncthreads();
        if (nt + 2 < 16) {
            const uint32_t NB = sb + ((nt & 1) ? SB1 : SB0);
            #pragma unroll
            for (int i = 0; i < 8; ++i) {
                int idx = tid + i * 512;
                int row = idx >> 5, ch = idx & 31;
                cp16(NB + row * 512 + ((ch ^ (row & 7)) << 4),
                     g_Wh + (size_t)((nt + 2) * 128 + row) * DIM + ch * 8);
            }
            cp_commit();
        }
    }

    // ---- per-token merge: 16 threads x top-3 -> global top-4 (smem, stride 49) ----
    __syncthreads();
    float* cv = (float*)sm;                      // 128 * 49 floats (25088 B)
    int*   ci = (int*)(sm + 25088);              // 128 * 49 ints
    const int slot = wn * 4 + (lane & 3);        // 0..15
    #pragma unroll
    for (int mi = 0; mi < 2; ++mi)
        #pragma unroll
        for (int h = 0; h < 2; ++h) {
            int r = mi * 2 + h;
            int tloc = wm * 32 + mi * 16 + h * 8 + (lane >> 2);
            cv[tloc * 49 + slot * 3 + 0] = v1[r];  ci[tloc * 49 + slot * 3 + 0] = i1[r];
            cv[tloc * 49 + slot * 3 + 1] = v2[r];  ci[tloc * 49 + slot * 3 + 1] = i2[r];
            cv[tloc * 49 + slot * 3 + 2] = v3[r];  ci[tloc * 49 + slot * 3 + 2] = i3[r];
        }
    __syncthreads();
    if (tid < 128) {
        float bv0 = 3.4e38f, bv1b = 3.4e38f, bv2b = 3.4e38f, bv3 = 3.4e38f;
        int   bx0 = 0, bx1 = 0, bx2 = 0, bx3 = 0;
        #pragma unroll
        for (int e = 0; e < 48; ++e) {
            float v = cv[tid * 49 + e];
            int   ix = ci[tid * 49 + e];
            if (v < bv3) {
                if (v < bv0) { bv3=bv2b; bx3=bx2; bv2b=bv1b; bx2=bx1; bv1b=bv0; bx1=bx0; bv0=v; bx0=ix; }
                else if (v < bv1b) { bv3=bv2b; bx3=bx2; bv2b=bv1b; bx2=bx1; bv1b=v; bx1=ix; }
                else if (v < bv2b) { bv3=bv2b; bx3=bx2; bv2b=v; bx2=ix; }
                else { bv3=v; bx3=ix; }
            }
        }
        g_cand4[n0 + tid] = make_int4(bx0, bx1, bx2, bx3);
    }
}

// ---------------- fused: exact rescore + loss + dw + encodings + q_out ----------------
// 1024 blocks (one per 64-token row) x 512 thr. Warp w owns tokens w*4..w*4+3.
__global__ void __launch_bounds__(512)
k_resq(const float* __restrict__ weight, float* __restrict__ out) {
    __shared__ float wrow[64 * 67];
    __shared__ int   idx_s[64];
    __shared__ float ls[16];
    const int tid = threadIdx.x;
    const int warp = tid >> 5, lane = tid & 31;
    const int blk = blockIdx.x;
    const int b = blk >> 6, h = blk & 63;
    const int n0 = b * HW + h * 64;

    float lacc = 0.0f;
    #pragma unroll
    for (int it = 0; it < 4; ++it) {
        int tok = n0 + warp * 4 + it;
        int4 cc = g_cand4[tok];
        const float* w0 = weight + (size_t)cc.x * DIM + lane;
        const float* w1 = weight + (size_t)cc.y * DIM + lane;
        const float* w2 = weight + (size_t)cc.z * DIM + lane;
        const float* w3 = weight + (size_t)cc.w * DIM + lane;
        float xv[8];
        float xn = 0.0f;
        float d0 = 0.0f, d1 = 0.0f, d2 = 0.0f, d3 = 0.0f;
        #pragma unroll
        for (int i = 0; i < 8; ++i) {
            xv[i] = g_Xf[(size_t)tok * DIM + lane + 32 * i];
            xn += xv[i] * xv[i];
        }
        #pragma unroll
        for (int i = 0; i < 8; ++i) {
            float a0 = __ldg(w0 + 32 * i);
            float a1 = __ldg(w1 + 32 * i);
            float a2 = __ldg(w2 + 32 * i);
            float a3 = __ldg(w3 + 32 * i);
            d0 += xv[i] * a0;
            d1 += xv[i] * a1;
            d2 += xv[i] * a2;
            d3 += xv[i] * a3;
        }
        #pragma unroll
        for (int o = 16; o > 0; o >>= 1) {
            xn += __shfl_xor_sync(0xffffffffu, xn, o);
            d0 += __shfl_xor_sync(0xffffffffu, d0, o);
            d1 += __shfl_xor_sync(0xffffffffu, d1, o);
            d2 += __shfl_xor_sync(0xffffffffu, d2, o);
            d3 += __shfl_xor_sync(0xffffffffu, d3, o);
        }
        float s0 = g_wnorm[cc.x] - 2.0f * d0;
        float s1 = g_wnorm[cc.y] - 2.0f * d1;
        float s2 = g_wnorm[cc.z] - 2.0f * d2;
        float s3 = g_wnorm[cc.w] - 2.0f * d3;
        float bs = s0; int bi = cc.x;
        if (s1 < bs || (s1 == bs && cc.y < bi)) { bs = s1; bi = cc.y; }
        if (s2 < bs || (s2 == bs && cc.z < bi)) { bs = s2; bi = cc.z; }
        if (s3 < bs || (s3 == bs && cc.w < bi)) { bs = s3; bi = cc.w; }
        // dw accumulation (coalesced REDs)
        float* dwr = g_dw + (size_t)bi * DIM + lane;
        #pragma unroll
        for (int i = 0; i < 8; ++i)
            atomicAdd(dwr + 32 * i, xv[i]);
        if (lane == 0) {
            idx_s[warp * 4 + it] = bi;
            atomicAdd(&g_counts[bi], 1);
            out[OFF_ENC + (long long)tok * KCB + bi] = 1.0f;
            lacc += bs + xn;          // == ||x - w||^2
        }
    }
    if (lane == 0) ls[warp] = lacc;
    __syncthreads();
    if (tid == 0) {
        float s = 0.0f;
        #pragma unroll
        for (int w = 0; w < 16; ++w) s += ls[w];
        atomicAdd(&g_loss, s);
    }

    // ---- quant phase: stage gathered rows, write q_out coalesced ----
    const int w = tid & 63, dg = tid >> 6;       // dg 0..7
    float* qbp = out + OFF_QOUT + (size_t)b * DHW + h * 64 + w;
    for (int c = 0; c < 4; ++c) {
        #pragma unroll
        for (int p = 0; p < 8; ++p) {
            int idx = tid + p * 512;
            int r = idx >> 6, d = idx & 63;
            wrow[r * 67 + d] = __ldg(weight + (size_t)idx_s[r] * DIM + c * 64 + d);
        }
        __syncthreads();
        #pragma unroll
        for (int s = 0; s < 8; ++s) {
            int dl = dg * 8 + s;
            int d = c * 64 + dl;
            __stcs(qbp + (size_t)d * HW, wrow[w * 67 + dl]);
        }
        __syncthreads();
    }
}

// ---------------- stats ----------------
__global__ void k_stats(const float* __restrict__ ecs, float* __restrict__ out) {
    __shared__ float sn[1024];
    __shared__ float sh[1024];
    int t = threadIdx.x;
    float c0 = (float)g_counts[t];
    float c1 = (float)g_counts[t + 1024];
    float cs0 = ecs[t] * DECAYF + OMD * c0;
    float cs1 = ecs[t + 1024] * DECAYF + OMD * c1;
    float p0 = c0 / 65536.0f, p1 = c1 / 65536.0f;
    sn[t] = cs0 + cs1;
    sh[t] = p0 * logf(p0 + 1e-10f) + p1 * logf(p1 + 1e-10f);
    __syncthreads();
    #pragma unroll
    for (int st = 512; st > 0; st >>= 1) {
        if (t < st) { sn[t] += sn[t + st]; sh[t] += sh[t + st]; }
        __syncthreads();
    }
    float n = sn[0];
    float denom = n + (float)KCB * EPSF;
    out[OFF_CS + t]        = (cs0 + EPSF) / denom * n;
    out[OFF_CS + t + 1024] = (cs1 + EPSF) / denom * n;
    if (t == 0) {
        out[OFF_PERP] = expf(-sh[0]);
        out[OFF_LOSS] = 0.25f * g_loss / 16777216.0f;
    }
}

// ---------------- EMA update ----------------
__global__ void k_ema(const float* __restrict__ emaw, float* __restrict__ out) {
    int i = blockIdx.x * 256 + threadIdx.x;
    float e = emaw[i] * DECAYF + OMD * g_dw[i];
    out[OFF_EMAW + i] = e;
    out[OFF_W + i]    = e / out[OFF_CS + (i >> 8)];
}

// ---------------- launch ----------------
extern "C" void kernel_launch(void* const* d_in, const int* in_sizes, int n_in,
                              void* d_out, int out_size) {
    const float* z    = (const float*)d_in[0];
    const float* wgt  = (const float*)d_in[1];
    const float* ecs  = (const float*)d_in[2];
    const float* emaw = (const float*)d_in[3];
    float* out = (float*)d_out;

    cudaFuncSetAttribute(k_gemm,   cudaFuncAttributeMaxDynamicSharedMemorySize, SMT);
    cudaFuncSetAttribute(k_prep_x, cudaFuncAttributeMaxDynamicSharedMemorySize, 64 * 260 * 4);

    k_prep_w <<<256, 256>>>(wgt);
    k_prep_x <<<1024, 256, 64 * 260 * 4>>>(z);
    k_gemm   <<<512, 512, SMT>>>(out);
    k_resq   <<<1024, 512>>>(wgt, out);
    k_stats  <<<1, 1024>>>(ecs, out);
    k_ema    <<<2048, 256>>>(emaw, out);
}

// round 14
// speedup vs baseline: 1.1204x; 1.0273x over previous
#include <cuda_runtime.h>
#include <cuda_fp16.h>
#include <math.h>
#include <stdint.h>

// ---------------- problem constants ----------------
#define NTOT   65536
#define KCB    2048
#define DIM    256
#define HW     4096
#define DHW    1048576

#define OFF_LOSS 0LL
#define OFF_QOUT 1LL
#define OFF_PERP 16777217LL
#define OFF_ENC  16777218LL
#define OFF_CS   150994946LL
#define OFF_EMAW 150996994LL
#define OFF_W    151521282LL

static const float DECAYF = 0.99f;
static const float OMD    = 0.01f;
static const float EPSF   = 1e-5f;

// ---------------- device scratch ----------------
__device__ __half g_Xh[NTOT * DIM];     // token-major fp16 x      (32MB)
__device__ __half g_Wh[KCB * DIM];      // code-major fp16 (-2w)   (1MB)
__device__ float  g_Xf[NTOT * DIM];     // token-major fp32 x      (64MB)
__device__ float  g_wnorm[KCB];
__device__ int    g_counts[KCB];
__device__ int4   g_cand4[NTOT];        // 4 exact-rescore candidates per token (1MB)
__device__ float  g_dw[KCB * DIM];
__device__ float  g_loss;               // accumulates sum(||x||^2) + sum(min score)

// ---------------- helpers ----------------
__device__ __forceinline__ uint32_t smem_u32(const void* p) {
    uint32_t a;
    asm("{ .reg .u64 t; cvta.to.shared.u64 t, %1; cvt.u32.u64 %0, t; }" : "=r"(a) : "l"(p));
    return a;
}
__device__ __forceinline__ void cp16(uint32_t dst, const void* src) {
    asm volatile("cp.async.cg.shared.global [%0], [%1], 16;" :: "r"(dst), "l"(src) : "memory");
}
__device__ __forceinline__ void cp_commit() { asm volatile("cp.async.commit_group;" ::: "memory"); }

__device__ __forceinline__ void ldm4(uint32_t a, uint32_t r[4]) {
    asm volatile("ldmatrix.sync.aligned.m8n8.x4.shared.b16 {%0,%1,%2,%3}, [%4];"
                 : "=r"(r[0]), "=r"(r[1]), "=r"(r[2]), "=r"(r[3]) : "r"(a));
}
// fp16-accumulate HMMA
__device__ __forceinline__ void mma16816h(uint32_t c[2], const uint32_t a[4],
                                          uint32_t b0, uint32_t b1) {
    asm volatile("mma.sync.aligned.m16n8k16.row.col.f16.f16.f16.f16 "
                 "{%0,%1},{%2,%3,%4,%5},{%6,%7},{%0,%1};"
                 : "+r"(c[0]), "+r"(c[1])
                 : "r"(a[0]), "r"(a[1]), "r"(a[2]), "r"(a[3]), "r"(b0), "r"(b1));
}

// ---------------- codebook prep: fp16(-2w) + norms + init ----------------
__global__ void k_prep_w(const float* __restrict__ weight) {
    int warp = threadIdx.x >> 5, lane = threadIdx.x & 31;
    int k = blockIdx.x * 8 + warp;               // 256 blocks
    float s = 0.0f;
    #pragma unroll
    for (int i = 0; i < 8; ++i) {
        int d = lane + i * 32;
        float v = weight[(size_t)k * DIM + d];
        g_Wh[(size_t)k * DIM + d] = __float2half(-2.0f * v);
        s += v * v;
    }
    #pragma unroll
    for (int o = 16; o > 0; o >>= 1) s += __shfl_down_sync(0xffffffffu, s, o);
    if (lane == 0) {
        g_wnorm[k] = s;
        g_counts[k] = 0;
        if (k == 0) g_loss = 0.0f;
    }
}

// ---------------- x prep: transpose + fp16 mirror + sum(x^2); zero dw ----------------
__global__ void k_prep_x(const float* __restrict__ z) {
    extern __shared__ float xs[];             // 64*260
    __shared__ float xred[256];
    const int tid = threadIdx.x;
    // zero g_dw (1024 blocks x 512 elems)
    g_dw[(size_t)blockIdx.x * 512 + tid] = 0.0f;
    g_dw[(size_t)blockIdx.x * 512 + 256 + tid] = 0.0f;

    const int n0 = blockIdx.x * 64;
    const int b = n0 >> 12, sp0 = n0 & 4095;
    const float* zb = z + (size_t)b * DHW + sp0;
    #pragma unroll
    for (int p = 0; p < 16; ++p) {
        int lin = tid + p * 256;
        int q = lin & 63, dq4 = lin >> 6;
        float4 v;
        v.x = zb[(dq4 * 4 + 0) * HW + q];
        v.y = zb[(dq4 * 4 + 1) * HW + q];
        v.z = zb[(dq4 * 4 + 2) * HW + q];
        v.w = zb[(dq4 * 4 + 3) * HW + q];
        *(float4*)(xs + q * 260 + dq4 * 4) = v;
    }
    __syncthreads();
    float la = 0.0f;
    #pragma unroll
    for (int p = 0; p < 64; ++p) {
        int lin = tid + p * 256;
        int q = lin >> 8, d = lin & 255;
        float v = xs[q * 260 + d];
        size_t t = (size_t)(n0 + q);
        g_Xh[t * DIM + d] = __float2half(v);
        g_Xf[t * DIM + d] = v;
        la += v * v;
    }
    xred[tid] = la;
    __syncthreads();
    #pragma unroll
    for (int st = 128; st > 0; st >>= 1) {
        if (tid < st) xred[tid] += xred[tid + st];
        __syncthreads();
    }
    if (tid == 0) atomicAdd(&g_loss, xred[0]);
}

// ---------------- HMMA argmin GEMM (fp16 accum) + enc zero-fill ----------------
// 512 CTAs x 512 thr (16 warps: 4m x 4n, warp tile 32x32). CTA = 128 tokens x
// 2048 codes, K=256. A resident (64KB, cp.async); B double-buffered (2x64KB).
// Per-thread top-3; 48 candidates per token merged to top-4.
#define SA  0
#define SB0 65536
#define SB1 131072
#define SMT 196608

__global__ void __launch_bounds__(512, 1)
k_gemm(float* __restrict__ out) {
    extern __shared__ char sm[];
    const uint32_t sb = smem_u32(sm);
    const int tid = threadIdx.x;
    const int lane = tid & 31, warp = tid >> 5;
    const int wm = warp & 3, wn = warp >> 2;      // 4m x 4n
    const int n0 = blockIdx.x * 128;
    float2* enc2 = (float2*)(out + OFF_ENC) + (size_t)blockIdx.x * 131072;

    // A tile (grouped with B0)
    #pragma unroll
    for (int i = 0; i < 8; ++i) {
        int idx = tid + i * 512;                 // 4096 chunks
        int row = idx >> 5, ch = idx & 31;
        cp16(sb + SA + row * 512 + ((ch ^ (row & 7)) << 4),
             g_Xh + (size_t)(n0 + row) * DIM + ch * 8);
    }
    // B tile 0
    #pragma unroll
    for (int i = 0; i < 8; ++i) {
        int idx = tid + i * 512;
        int row = idx >> 5, ch = idx & 31;
        cp16(sb + SB0 + row * 512 + ((ch ^ (row & 7)) << 4),
             g_Wh + (size_t)row * DIM + ch * 8);
    }
    cp_commit();
    // B tile 1
    #pragma unroll
    for (int i = 0; i < 8; ++i) {
        int idx = tid + i * 512;
        int row = idx >> 5, ch = idx & 31;
        cp16(sb + SB1 + row * 512 + ((ch ^ (row & 7)) << 4),
             g_Wh + (size_t)(128 + row) * DIM + ch * 8);
    }
    cp_commit();

    // per-thread top-3 for 4 owned token slots (r = mi*2 + h)
    float v1[4], v2[4], v3[4];
    int   i1[4], i2[4], i3[4];
    #pragma unroll
    for (int r = 0; r < 4; ++r) {
        v1[r] = 3.4e38f; v2[r] = 3.4e38f; v3[r] = 3.4e38f;
        i1[r] = 0; i2[r] = 0; i3[r] = 0;
    }

    const float2 zz = make_float2(0.f, 0.f);

    for (int nt = 0; nt < 16; ++nt) {
        if (nt < 15) asm volatile("cp.async.wait_group 1;" ::: "memory");
        else         asm volatile("cp.async.wait_group 0;" ::: "memory");
        __syncthreads();
        const uint32_t BB = sb + ((nt & 1) ? SB1 : SB0);

        uint32_t c[2][4][2];
        #pragma unroll
        for (int mi = 0; mi < 2; ++mi)
            #pragma unroll
            for (int ni = 0; ni < 4; ++ni) { c[mi][ni][0] = 0u; c[mi][ni][1] = 0u; }

        #pragma unroll
        for (int ks = 0; ks < 16; ++ks) {
            uint32_t a[2][4];
            #pragma unroll
            for (int mi = 0; mi < 2; ++mi) {
                int row = wm * 32 + mi * 16 + (lane & 15);
                int ch = ks * 2 + (lane >> 4);
                ldm4(sb + SA + row * 512 + ((ch ^ (row & 7)) << 4), a[mi]);
            }
            // B: non-trans ldmatrix on code-major smem; two 16-code groups.
            uint32_t b0[4], b1[4];
            {
                int code = wn * 32 + ((lane & 16) >> 1) + (lane & 7);
                int ch = ks * 2 + ((lane >> 3) & 1);
                ldm4(BB + code * 512 + ((ch ^ (code & 7)) << 4), b0);
                code += 16;
                ldm4(BB + code * 512 + ((ch ^ (code & 7)) << 4), b1);
            }
            #pragma unroll
            for (int mi = 0; mi < 2; ++mi) {
                mma16816h(c[mi][0], a[mi], b0[0], b0[1]);
                mma16816h(c[mi][1], a[mi], b0[2], b0[3]);
                mma16816h(c[mi][2], a[mi], b1[0], b1[1]);
                mma16816h(c[mi][3], a[mi], b1[2], b1[3]);
            }
        }

        // zero 16 float2 chunks of this CTA's encodings slice (streaming)
        #pragma unroll
        for (int j = 0; j < 16; ++j)
            __stcs(enc2 + (size_t)(nt * 16 + j) * 512 + tid, zz);

        // fold: score = wnorm + acc  (acc = x . (-2w), fp16 pair); top-3 insert
        #pragma unroll
        for (int ni = 0; ni < 4; ++ni) {
            int col = nt * 128 + wn * 32 + ni * 8 + (lane & 3) * 2;
            float2 wn2 = *(const float2*)&g_wnorm[col];
            #pragma unroll
            for (int mi = 0; mi < 2; ++mi) {
                #pragma unroll
                for (int h = 0; h < 2; ++h) {
                    int r = mi * 2 + h;
                    float2 cf = __half22float2(*(__half2*)&c[mi][ni][h]);
                    float s0 = wn2.x + cf.x;
                    float s1 = wn2.y + cf.y;
                    if (s0 < v3[r]) {
                        if (s0 < v1[r]) { v3[r]=v2[r]; i3[r]=i2[r]; v2[r]=v1[r]; i2[r]=i1[r]; v1[r]=s0; i1[r]=col; }
                        else if (s0 < v2[r]) { v3[r]=v2[r]; i3[r]=i2[r]; v2[r]=s0; i2[r]=col; }
                        else { v3[r]=s0; i3[r]=col; }
                    }
                    if (s1 < v3[r]) {
                        if (s1 < v1[r]) { v3[r]=v2[r]; i3[r]=i2[r]; v2[r]=v1[r]; i2[r]=i1[r]; v1[r]=s1; i1[r]=col+1; }
                        else if (s1 < v2[r]) { v3[r]=v2[r]; i3[r]=i2[r]; v2[r]=s1; i2[r]=col+1; }
                        else { v3[r]=s1; i3[r]=col+1; }
                    }
                }
            }
        }

        __syncthreads();
        if (nt + 2 < 16) {
            const uint32_t NB = sb + ((nt & 1) ? SB1 : SB0);
            #pragma unroll
            for (int i = 0; i < 8; ++i) {
                int idx = tid + i * 512;
                int row = idx >> 5, ch = idx & 31;
                cp16(NB + row * 512 + ((ch ^ (row & 7)) << 4),
                     g_Wh + (size_t)((nt + 2) * 128 + row) * DIM + ch * 8);
            }
            cp_commit();
        }
    }

    // ---- per-token merge: 16 threads x top-3 -> global top-4 (smem, stride 49) ----
    __syncthreads();
    float* cv = (float*)sm;                      // 128 * 49 floats (25088 B)
    int*   ci = (int*)(sm + 25088);              // 128 * 49 ints
    const int slot = wn * 4 + (lane & 3);        // 0..15
    #pragma unroll
    for (int mi = 0; mi < 2; ++mi)
        #pragma unroll
        for (int h = 0; h < 2; ++h) {
            int r = mi * 2 + h;
            int tloc = wm * 32 + mi * 16 + h * 8 + (lane >> 2);
            cv[tloc * 49 + slot * 3 + 0] = v1[r];  ci[tloc * 49 + slot * 3 + 0] = i1[r];
            cv[tloc * 49 + slot * 3 + 1] = v2[r];  ci[tloc * 49 + slot * 3 + 1] = i2[r];
            cv[tloc * 49 + slot * 3 + 2] = v3[r];  ci[tloc * 49 + slot * 3 + 2] = i3[r];
        }
    __syncthreads();
    if (tid < 128) {
        float bv0 = 3.4e38f, bv1b = 3.4e38f, bv2b = 3.4e38f, bv3 = 3.4e38f;
        int   bx0 = 0, bx1 = 0, bx2 = 0, bx3 = 0;
        #pragma unroll
        for (int e = 0; e < 48; ++e) {
            float v = cv[tid * 49 + e];
            int   ix = ci[tid * 49 + e];
            if (v < bv3) {
                if (v < bv0) { bv3=bv2b; bx3=bx2; bv2b=bv1b; bx2=bx1; bv1b=bv0; bx1=bx0; bv0=v; bx0=ix; }
                else if (v < bv1b) { bv3=bv2b; bx3=bx2; bv2b=bv1b; bx2=bx1; bv1b=v; bx1=ix; }
                else if (v < bv2b) { bv3=bv2b; bx3=bx2; bv2b=v; bx2=ix; }
                else { bv3=v; bx3=ix; }
            }
        }
        g_cand4[n0 + tid] = make_int4(bx0, bx1, bx2, bx3);
    }
}

// ---------------- fused: exact rescore + loss + dw + encodings + q_out ----------------
// 1024 blocks (one per 64-token row) x 512 thr. Warp w owns tokens w*4..w*4+3.
// ||x||^2 already accumulated into g_loss by k_prep_x; only min-score added here.
__global__ void __launch_bounds__(512)
k_resq(const float* __restrict__ weight, float* __restrict__ out) {
    __shared__ float wrow[64 * 67];
    __shared__ int   idx_s[64];
    __shared__ float ls[16];
    const int tid = threadIdx.x;
    const int warp = tid >> 5, lane = tid & 31;
    const int blk = blockIdx.x;
    const int b = blk >> 6, h = blk & 63;
    const int n0 = b * HW + h * 64;

    float lacc = 0.0f;
    #pragma unroll
    for (int it = 0; it < 4; ++it) {
        int tok = n0 + warp * 4 + it;
        int4 cc = g_cand4[tok];
        const float* w0 = weight + (size_t)cc.x * DIM + lane;
        const float* w1 = weight + (size_t)cc.y * DIM + lane;
        const float* w2 = weight + (size_t)cc.z * DIM + lane;
        const float* w3 = weight + (size_t)cc.w * DIM + lane;
        float xv[8];
        float d0 = 0.0f, d1 = 0.0f, d2 = 0.0f, d3 = 0.0f;
        #pragma unroll
        for (int i = 0; i < 8; ++i)
            xv[i] = g_Xf[(size_t)tok * DIM + lane + 32 * i];
        #pragma unroll
        for (int i = 0; i < 8; ++i) {
            float a0 = __ldg(w0 + 32 * i);
            float a1 = __ldg(w1 + 32 * i);
            float a2 = __ldg(w2 + 32 * i);
            float a3 = __ldg(w3 + 32 * i);
            d0 += xv[i] * a0;
            d1 += xv[i] * a1;
            d2 += xv[i] * a2;
            d3 += xv[i] * a3;
        }
        #pragma unroll
        for (int o = 16; o > 0; o >>= 1) {
            d0 += __shfl_xor_sync(0xffffffffu, d0, o);
            d1 += __shfl_xor_sync(0xffffffffu, d1, o);
            d2 += __shfl_xor_sync(0xffffffffu, d2, o);
            d3 += __shfl_xor_sync(0xffffffffu, d3, o);
        }
        float s0 = g_wnorm[cc.x] - 2.0f * d0;
        float s1 = g_wnorm[cc.y] - 2.0f * d1;
        float s2 = g_wnorm[cc.z] - 2.0f * d2;
        float s3 = g_wnorm[cc.w] - 2.0f * d3;
        float bs = s0; int bi = cc.x;
        if (s1 < bs || (s1 == bs && cc.y < bi)) { bs = s1; bi = cc.y; }
        if (s2 < bs || (s2 == bs && cc.z < bi)) { bs = s2; bi = cc.z; }
        if (s3 < bs || (s3 == bs && cc.w < bi)) { bs = s3; bi = cc.w; }
        // dw accumulation (coalesced REDs)
        float* dwr = g_dw + (size_t)bi * DIM + lane;
        #pragma unroll
        for (int i = 0; i < 8; ++i)
            atomicAdd(dwr + 32 * i, xv[i]);
        if (lane == 0) {
            idx_s[warp * 4 + it] = bi;
            atomicAdd(&g_counts[bi], 1);
            out[OFF_ENC + (long long)tok * KCB + bi] = 1.0f;
            lacc += bs;               // ||x||^2 part added in prep_x
        }
    }
    if (lane == 0) ls[warp] = lacc;
    __syncthreads();
    if (tid == 0) {
        float s = 0.0f;
        #pragma unroll
        for (int w = 0; w < 16; ++w) s += ls[w];
        atomicAdd(&g_loss, s);
    }

    // ---- quant phase: stage gathered rows, write q_out coalesced ----
    const int w = tid & 63, dg = tid >> 6;       // dg 0..7
    float* qbp = out + OFF_QOUT + (size_t)b * DHW + h * 64 + w;
    for (int c = 0; c < 4; ++c) {
        #pragma unroll
        for (int p = 0; p < 8; ++p) {
            int idx = tid + p * 512;
            int r = idx >> 6, d = idx & 63;
            wrow[r * 67 + d] = __ldg(weight + (size_t)idx_s[r] * DIM + c * 64 + d);
        }
        __syncthreads();
        #pragma unroll
        for (int s = 0; s < 8; ++s) {
            int dl = dg * 8 + s;
            int d = c * 64 + dl;
            __stcs(qbp + (size_t)d * HW, wrow[w * 67 + dl]);
        }
        __syncthreads();
    }
}

// ---------------- stats ----------------
__global__ void k_stats(const float* __restrict__ ecs, float* __restrict__ out) {
    __shared__ float sn[1024];
    __shared__ float sh[1024];
    int t = threadIdx.x;
    float c0 = (float)g_counts[t];
    float c1 = (float)g_counts[t + 1024];
    float cs0 = ecs[t] * DECAYF + OMD * c0;
    float cs1 = ecs[t + 1024] * DECAYF + OMD * c1;
    float p0 = c0 / 65536.0f, p1 = c1 / 65536.0f;
    sn[t] = cs0 + cs1;
    sh[t] = p0 * logf(p0 + 1e-10f) + p1 * logf(p1 + 1e-10f);
    __syncthreads();
    #pragma unroll
    for (int st = 512; st > 0; st >>= 1) {
        if (t < st) { sn[t] += sn[t + st]; sh[t] += sh[t + st]; }
        __syncthreads();
    }
    float n = sn[0];
    float denom = n + (float)KCB * EPSF;
    out[OFF_CS + t]        = (cs0 + EPSF) / denom * n;
    out[OFF_CS + t + 1024] = (cs1 + EPSF) / denom * n;
    if (t == 0) {
        out[OFF_PERP] = expf(-sh[0]);
        out[OFF_LOSS] = 0.25f * g_loss / 16777216.0f;
    }
}

// ---------------- EMA update ----------------
__global__ void k_ema(const float* __restrict__ emaw, float* __restrict__ out) {
    int i = blockIdx.x * 256 + threadIdx.x;
    float e = emaw[i] * DECAYF + OMD * g_dw[i];
    out[OFF_EMAW + i] = e;
    out[OFF_W + i]    = e / out[OFF_CS + (i >> 8)];
}

// ---------------- launch ----------------
extern "C" void kernel_launch(void* const* d_in, const int* in_sizes, int n_in,
                              void* d_out, int out_size) {
    const float* z    = (const float*)d_in[0];
    const float* wgt  = (const float*)d_in[1];
    const float* ecs  = (const float*)d_in[2];
    const float* emaw = (const float*)d_in[3];
    float* out = (float*)d_out;

    cudaFuncSetAttribute(k_gemm,   cudaFuncAttributeMaxDynamicSharedMemorySize, SMT);
    cudaFuncSetAttribute(k_prep_x, cudaFuncAttributeMaxDynamicSharedMemorySize, 64 * 260 * 4);

    k_prep_w <<<256, 256>>>(wgt);
    k_prep_x <<<1024, 256, 64 * 260 * 4>>>(z);
    k_gemm   <<<512, 512, SMT>>>(out);
    k_resq   <<<1024, 512>>>(wgt, out);
    k_stats  <<<1, 1024>>>(ecs, out);
    k_ema    <<<2048, 256>>>(emaw, out);
}

// round 15
// speedup vs baseline: 1.1204x; 1.0001x over previous
#include <cuda_runtime.h>
#include <cuda_fp16.h>
#include <math.h>
#include <stdint.h>

// ---------------- problem constants ----------------
#define NTOT   65536
#define KCB    2048
#define DIM    256
#define HW     4096
#define DHW    1048576

#define OFF_LOSS 0LL
#define OFF_QOUT 1LL
#define OFF_PERP 16777217LL
#define OFF_ENC  16777218LL
#define OFF_CS   150994946LL
#define OFF_EMAW 150996994LL
#define OFF_W    151521282LL

static const float DECAYF = 0.99f;
static const float OMD    = 0.01f;
static const float EPSF   = 1e-5f;

// ---------------- device scratch ----------------
__device__ __half g_Wh[KCB * DIM];      // code-major fp16 (-2w)   (1MB)
__device__ float  g_Xf[NTOT * DIM];     // token-major fp32 x      (64MB)
__device__ float  g_wnorm[KCB];
__device__ int    g_counts[KCB];
__device__ int4   g_cand4[NTOT];        // 4 exact-rescore candidates per token (1MB)
__device__ float  g_dw[KCB * DIM];
__device__ float  g_loss;               // sum(||x||^2) + sum(min score)

// ---------------- helpers ----------------
__device__ __forceinline__ uint32_t smem_u32(const void* p) {
    uint32_t a;
    asm("{ .reg .u64 t; cvta.to.shared.u64 t, %1; cvt.u32.u64 %0, t; }" : "=r"(a) : "l"(p));
    return a;
}
__device__ __forceinline__ uint32_t h2u(__half2 h) {
    union { __half2 h; uint32_t u; } c; c.h = h; return c.u;
}
__device__ __forceinline__ void cp16(uint32_t dst, const void* src) {
    asm volatile("cp.async.cg.shared.global [%0], [%1], 16;" :: "r"(dst), "l"(src) : "memory");
}
__device__ __forceinline__ void cp_commit() { asm volatile("cp.async.commit_group;" ::: "memory"); }

__device__ __forceinline__ void ldm4(uint32_t a, uint32_t r[4]) {
    asm volatile("ldmatrix.sync.aligned.m8n8.x4.shared.b16 {%0,%1,%2,%3}, [%4];"
                 : "=r"(r[0]), "=r"(r[1]), "=r"(r[2]), "=r"(r[3]) : "r"(a));
}
// fp16-accumulate HMMA
__device__ __forceinline__ void mma16816h(uint32_t c[2], const uint32_t a[4],
                                          uint32_t b0, uint32_t b1) {
    asm volatile("mma.sync.aligned.m16n8k16.row.col.f16.f16.f16.f16 "
                 "{%0,%1},{%2,%3,%4,%5},{%6,%7},{%0,%1};"
                 : "+r"(c[0]), "+r"(c[1])
                 : "r"(a[0]), "r"(a[1]), "r"(a[2]), "r"(a[3]), "r"(b0), "r"(b1));
}

// ---------------- codebook prep: fp16(-2w) + norms + init + dw zero ----------------
__global__ void k_prep_w(const float* __restrict__ weight) {
    int tid = threadIdx.x;
    int warp = tid >> 5, lane = tid & 31;
    int k = blockIdx.x * 8 + warp;               // 256 blocks
    // zero g_dw: 2048 floats per block
    #pragma unroll
    for (int i = 0; i < 8; ++i)
        g_dw[(size_t)blockIdx.x * 2048 + tid + i * 256] = 0.0f;
    float s = 0.0f;
    #pragma unroll
    for (int i = 0; i < 8; ++i) {
        int d = lane + i * 32;
        float v = weight[(size_t)k * DIM + d];
        g_Wh[(size_t)k * DIM + d] = __float2half(-2.0f * v);
        s += v * v;
    }
    #pragma unroll
    for (int o = 16; o > 0; o >>= 1) s += __shfl_down_sync(0xffffffffu, s, o);
    if (lane == 0) {
        g_wnorm[k] = s;
        g_counts[k] = 0;
        if (k == 0) g_loss = 0.0f;
    }
}

// ---------------- HMMA argmin GEMM + fused x-prep + enc zero-fill ----------------
// 512 CTAs x 512 thr (16 warps: 4m x 4n, warp tile 32x32). CTA = 128 tokens x
// 2048 codes, K=256. Prologue: reads its z slice, writes g_Xf, converts fp16
// into swizzled A tile, accumulates sum(x^2). B double-buffered (2x64KB).
// Per-thread top-3; 48 candidates per token merged to top-4.
#define SA  0
#define SB0 65536
#define SB1 131072
#define SMT 196608

__global__ void __launch_bounds__(512, 1)
k_gemm(const float* __restrict__ z, float* __restrict__ out) {
    extern __shared__ char sm[];
    const uint32_t sb = smem_u32(sm);
    const int tid = threadIdx.x;
    const int lane = tid & 31, warp = tid >> 5;
    const int wm = warp & 3, wn = warp >> 2;      // 4m x 4n
    const int n0 = blockIdx.x * 128;
    float2* enc2 = (float2*)(out + OFF_ENC) + (size_t)blockIdx.x * 131072;

    // ---- fused x prep: z -> staging smem -> (SA fp16 swizzled, g_Xf, sum x^2) ----
    {
        float* xs = (float*)(sm + SB0);           // 64*260 floats staging (66.5KB)
        const int bb = n0 >> 12, sp0 = n0 & 4095;
        const float* zb = z + (size_t)bb * DHW + sp0;
        float la = 0.0f;
        #pragma unroll
        for (int half = 0; half < 2; ++half) {
            const float* zh = zb + half * 64;
            #pragma unroll
            for (int p = 0; p < 8; ++p) {
                int lin = tid + p * 512;          // 4096 = 64 q x 64 dq4
                int q = lin & 63, dq4 = lin >> 6;
                float4 v;
                v.x = zh[(dq4 * 4 + 0) * HW + q];
                v.y = zh[(dq4 * 4 + 1) * HW + q];
                v.z = zh[(dq4 * 4 + 2) * HW + q];
                v.w = zh[(dq4 * 4 + 3) * HW + q];
                *(float4*)(xs + q * 260 + dq4 * 4) = v;
            }
            __syncthreads();
            #pragma unroll
            for (int p = 0; p < 4; ++p) {
                int lin = tid + p * 512;          // 2048 = 64 q x 32 ch
                int q = lin >> 5, ch = lin & 31;
                const float* src = xs + q * 260 + ch * 8;
                float4 f0 = *(const float4*)src;
                float4 f1 = *(const float4*)(src + 4);
                la += f0.x * f0.x + f0.y * f0.y + f0.z * f0.z + f0.w * f0.w
                    + f1.x * f1.x + f1.y * f1.y + f1.z * f1.z + f1.w * f1.w;
                uint4 v;
                v.x = h2u(__floats2half2_rn(f0.x, f0.y));
                v.y = h2u(__floats2half2_rn(f0.z, f0.w));
                v.z = h2u(__floats2half2_rn(f1.x, f1.y));
                v.w = h2u(__floats2half2_rn(f1.z, f1.w));
                int row = half * 64 + q;
                *(uint4*)(sm + SA + row * 512 + ((ch ^ (row & 7)) << 4)) = v;
                float* dst = g_Xf + (size_t)(n0 + row) * DIM + ch * 8;
                *(float4*)dst = f0;
                *(float4*)(dst + 4) = f1;
            }
            __syncthreads();
        }
        #pragma unroll
        for (int o = 16; o > 0; o >>= 1) la += __shfl_xor_sync(0xffffffffu, la, o);
        if (lane == 0) atomicAdd(&g_loss, la);
    }

    // B tile 0
    #pragma unroll
    for (int i = 0; i < 8; ++i) {
        int idx = tid + i * 512;
        int row = idx >> 5, ch = idx & 31;
        cp16(sb + SB0 + row * 512 + ((ch ^ (row & 7)) << 4),
             g_Wh + (size_t)row * DIM + ch * 8);
    }
    cp_commit();
    // B tile 1
    #pragma unroll
    for (int i = 0; i < 8; ++i) {
        int idx = tid + i * 512;
        int row = idx >> 5, ch = idx & 31;
        cp16(sb + SB1 + row * 512 + ((ch ^ (row & 7)) << 4),
             g_Wh + (size_t)(128 + row) * DIM + ch * 8);
    }
    cp_commit();

    // per-thread top-3 for 4 owned token slots (r = mi*2 + h)
    float v1[4], v2[4], v3[4];
    int   i1[4], i2[4], i3[4];
    #pragma unroll
    for (int r = 0; r < 4; ++r) {
        v1[r] = 3.4e38f; v2[r] = 3.4e38f; v3[r] = 3.4e38f;
        i1[r] = 0; i2[r] = 0; i3[r] = 0;
    }

    const float2 zz = make_float2(0.f, 0.f);

    for (int nt = 0; nt < 16; ++nt) {
        if (nt < 15) asm volatile("cp.async.wait_group 1;" ::: "memory");
        else         asm volatile("cp.async.wait_group 0;" ::: "memory");
        __syncthreads();
        const uint32_t BB = sb + ((nt & 1) ? SB1 : SB0);

        uint32_t c[2][4][2];
        #pragma unroll
        for (int mi = 0; mi < 2; ++mi)
            #pragma unroll
            for (int ni = 0; ni < 4; ++ni) { c[mi][ni][0] = 0u; c[mi][ni][1] = 0u; }

        #pragma unroll
        for (int ks = 0; ks < 16; ++ks) {
            uint32_t a[2][4];
            #pragma unroll
            for (int mi = 0; mi < 2; ++mi) {
                int row = wm * 32 + mi * 16 + (lane & 15);
                int ch = ks * 2 + (lane >> 4);
                ldm4(sb + SA + row * 512 + ((ch ^ (row & 7)) << 4), a[mi]);
            }
            // B: non-trans ldmatrix on code-major smem; two 16-code groups.
            uint32_t b0[4], b1[4];
            {
                int code = wn * 32 + ((lane & 16) >> 1) + (lane & 7);
                int ch = ks * 2 + ((lane >> 3) & 1);
                ldm4(BB + code * 512 + ((ch ^ (code & 7)) << 4), b0);
                code += 16;
                ldm4(BB + code * 512 + ((ch ^ (code & 7)) << 4), b1);
            }
            #pragma unroll
            for (int mi = 0; mi < 2; ++mi) {
                mma16816h(c[mi][0], a[mi], b0[0], b0[1]);
                mma16816h(c[mi][1], a[mi], b0[2], b0[3]);
                mma16816h(c[mi][2], a[mi], b1[0], b1[1]);
                mma16816h(c[mi][3], a[mi], b1[2], b1[3]);
            }
        }

        // zero 16 float2 chunks of this CTA's encodings slice (streaming)
        #pragma unroll
        for (int j = 0; j < 16; ++j)
            __stcs(enc2 + (size_t)(nt * 16 + j) * 512 + tid, zz);

        // fold: score = wnorm + acc  (acc = x . (-2w), fp16 pair); top-3 insert
        #pragma unroll
        for (int ni = 0; ni < 4; ++ni) {
            int col = nt * 128 + wn * 32 + ni * 8 + (lane & 3) * 2;
            float2 wn2 = *(const float2*)&g_wnorm[col];
            #pragma unroll
            for (int mi = 0; mi < 2; ++mi) {
                #pragma unroll
                for (int h = 0; h < 2; ++h) {
                    int r = mi * 2 + h;
                    float2 cf = __half22float2(*(__half2*)&c[mi][ni][h]);
                    float s0 = wn2.x + cf.x;
                    float s1 = wn2.y + cf.y;
                    if (s0 < v3[r]) {
                        if (s0 < v1[r]) { v3[r]=v2[r]; i3[r]=i2[r]; v2[r]=v1[r]; i2[r]=i1[r]; v1[r]=s0; i1[r]=col; }
                        else if (s0 < v2[r]) { v3[r]=v2[r]; i3[r]=i2[r]; v2[r]=s0; i2[r]=col; }
                        else { v3[r]=s0; i3[r]=col; }
                    }
                    if (s1 < v3[r]) {
                        if (s1 < v1[r]) { v3[r]=v2[r]; i3[r]=i2[r]; v2[r]=v1[r]; i2[r]=i1[r]; v1[r]=s1; i1[r]=col+1; }
                        else if (s1 < v2[r]) { v3[r]=v2[r]; i3[r]=i2[r]; v2[r]=s1; i2[r]=col+1; }
                        else { v3[r]=s1; i3[r]=col+1; }
                    }
                }
            }
        }

        __syncthreads();
        if (nt + 2 < 16) {
            const uint32_t NB = sb + ((nt & 1) ? SB1 : SB0);
            #pragma unroll
            for (int i = 0; i < 8; ++i) {
                int idx = tid + i * 512;
                int row = idx >> 5, ch = idx & 31;
                cp16(NB + row * 512 + ((ch ^ (row & 7)) << 4),
                     g_Wh + (size_t)((nt + 2) * 128 + row) * DIM + ch * 8);
            }
            cp_commit();
        }
    }

    // ---- per-token merge: 16 threads x top-3 -> global top-4 (smem, stride 49) ----
    __syncthreads();
    float* cv = (float*)sm;                      // 128 * 49 floats (25088 B)
    int*   ci = (int*)(sm + 25088);              // 128 * 49 ints
    const int slot = wn * 4 + (lane & 3);        // 0..15
    #pragma unroll
    for (int mi = 0; mi < 2; ++mi)
        #pragma unroll
        for (int h = 0; h < 2; ++h) {
            int r = mi * 2 + h;
            int tloc = wm * 32 + mi * 16 + h * 8 + (lane >> 2);
            cv[tloc * 49 + slot * 3 + 0] = v1[r];  ci[tloc * 49 + slot * 3 + 0] = i1[r];
            cv[tloc * 49 + slot * 3 + 1] = v2[r];  ci[tloc * 49 + slot * 3 + 1] = i2[r];
            cv[tloc * 49 + slot * 3 + 2] = v3[r];  ci[tloc * 49 + slot * 3 + 2] = i3[r];
        }
    __syncthreads();
    if (tid < 128) {
        float bv0 = 3.4e38f, bv1b = 3.4e38f, bv2b = 3.4e38f, bv3 = 3.4e38f;
        int   bx0 = 0, bx1 = 0, bx2 = 0, bx3 = 0;
        #pragma unroll
        for (int e = 0; e < 48; ++e) {
            float v = cv[tid * 49 + e];
            int   ix = ci[tid * 49 + e];
            if (v < bv3) {
                if (v < bv0) { bv3=bv2b; bx3=bx2; bv2b=bv1b; bx2=bx1; bv1b=bv0; bx1=bx0; bv0=v; bx0=ix; }
                else if (v < bv1b) { bv3=bv2b; bx3=bx2; bv2b=bv1b; bx2=bx1; bv1b=v; bx1=ix; }
                else if (v < bv2b) { bv3=bv2b; bx3=bx2; bv2b=v; bx2=ix; }
                else { bv3=v; bx3=ix; }
            }
        }
        g_cand4[n0 + tid] = make_int4(bx0, bx1, bx2, bx3);
    }
}

// ---------------- fused: exact rescore + loss + dw + encodings + q_out ----------------
// 1024 blocks (one per 64-token row) x 512 thr. Warp w owns tokens w*4..w*4+3.
__global__ void __launch_bounds__(512)
k_resq(const float* __restrict__ weight, float* __restrict__ out) {
    __shared__ float wrow[64 * 67];
    __shared__ int   idx_s[64];
    __shared__ float ls[16];
    const int tid = threadIdx.x;
    const int warp = tid >> 5, lane = tid & 31;
    const int blk = blockIdx.x;
    const int b = blk >> 6, h = blk & 63;
    const int n0 = b * HW + h * 64;

    float lacc = 0.0f;
    #pragma unroll
    for (int it = 0; it < 4; ++it) {
        int tok = n0 + warp * 4 + it;
        int4 cc = g_cand4[tok];
        const float* w0 = weight + (size_t)cc.x * DIM + lane;
        const float* w1 = weight + (size_t)cc.y * DIM + lane;
        const float* w2 = weight + (size_t)cc.z * DIM + lane;
        const float* w3 = weight + (size_t)cc.w * DIM + lane;
        float xv[8];
        float d0 = 0.0f, d1 = 0.0f, d2 = 0.0f, d3 = 0.0f;
        #pragma unroll
        for (int i = 0; i < 8; ++i)
            xv[i] = g_Xf[(size_t)tok * DIM + lane + 32 * i];
        #pragma unroll
        for (int i = 0; i < 8; ++i) {
            float a0 = __ldg(w0 + 32 * i);
            float a1 = __ldg(w1 + 32 * i);
            float a2 = __ldg(w2 + 32 * i);
            float a3 = __ldg(w3 + 32 * i);
            d0 += xv[i] * a0;
            d1 += xv[i] * a1;
            d2 += xv[i] * a2;
            d3 += xv[i] * a3;
        }
        #pragma unroll
        for (int o = 16; o > 0; o >>= 1) {
            d0 += __shfl_xor_sync(0xffffffffu, d0, o);
            d1 += __shfl_xor_sync(0xffffffffu, d1, o);
            d2 += __shfl_xor_sync(0xffffffffu, d2, o);
            d3 += __shfl_xor_sync(0xffffffffu, d3, o);
        }
        float s0 = g_wnorm[cc.x] - 2.0f * d0;
        float s1 = g_wnorm[cc.y] - 2.0f * d1;
        float s2 = g_wnorm[cc.z] - 2.0f * d2;
        float s3 = g_wnorm[cc.w] - 2.0f * d3;
        float bs = s0; int bi = cc.x;
        if (s1 < bs || (s1 == bs && cc.y < bi)) { bs = s1; bi = cc.y; }
        if (s2 < bs || (s2 == bs && cc.z < bi)) { bs = s2; bi = cc.z; }
        if (s3 < bs || (s3 == bs && cc.w < bi)) { bs = s3; bi = cc.w; }
        // dw accumulation (coalesced REDs)
        float* dwr = g_dw + (size_t)bi * DIM + lane;
        #pragma unroll
        for (int i = 0; i < 8; ++i)
            atomicAdd(dwr + 32 * i, xv[i]);
        if (lane == 0) {
            idx_s[warp * 4 + it] = bi;
            atomicAdd(&g_counts[bi], 1);
            out[OFF_ENC + (long long)tok * KCB + bi] = 1.0f;
            lacc += bs;               // ||x||^2 part added in gemm prologue
        }
    }
    if (lane == 0) ls[warp] = lacc;
    __syncthreads();
    if (tid == 0) {
        float s = 0.0f;
        #pragma unroll
        for (int w = 0; w < 16; ++w) s += ls[w];
        atomicAdd(&g_loss, s);
    }

    // ---- quant phase: stage gathered rows, write q_out coalesced ----
    const int w = tid & 63, dg = tid >> 6;       // dg 0..7
    float* qbp = out + OFF_QOUT + (size_t)b * DHW + h * 64 + w;
    for (int c = 0; c < 4; ++c) {
        #pragma unroll
        for (int p = 0; p < 8; ++p) {
            int idx = tid + p * 512;
            int r = idx >> 6, d = idx & 63;
            wrow[r * 67 + d] = __ldg(weight + (size_t)idx_s[r] * DIM + c * 64 + d);
        }
        __syncthreads();
        #pragma unroll
        for (int s = 0; s < 8; ++s) {
            int dl = dg * 8 + s;
            int d = c * 64 + dl;
            __stcs(qbp + (size_t)d * HW, wrow[w * 67 + dl]);
        }
        __syncthreads();
    }
}

// ---------------- stats ----------------
__global__ void k_stats(const float* __restrict__ ecs, float* __restrict__ out) {
    __shared__ float sn[1024];
    __shared__ float sh[1024];
    int t = threadIdx.x;
    float c0 = (float)g_counts[t];
    float c1 = (float)g_counts[t + 1024];
    float cs0 = ecs[t] * DECAYF + OMD * c0;
    float cs1 = ecs[t + 1024] * DECAYF + OMD * c1;
    float p0 = c0 / 65536.0f, p1 = c1 / 65536.0f;
    sn[t] = cs0 + cs1;
    sh[t] = p0 * logf(p0 + 1e-10f) + p1 * logf(p1 + 1e-10f);
    __syncthreads();
    #pragma unroll
    for (int st = 512; st > 0; st >>= 1) {
        if (t < st) { sn[t] += sn[t + st]; sh[t] += sh[t + st]; }
        __syncthreads();
    }
    float n = sn[0];
    float denom = n + (float)KCB * EPSF;
    out[OFF_CS + t]        = (cs0 + EPSF) / denom * n;
    out[OFF_CS + t + 1024] = (cs1 + EPSF) / denom * n;
    if (t == 0) {
        out[OFF_PERP] = expf(-sh[0]);
        out[OFF_LOSS] = 0.25f * g_loss / 16777216.0f;
    }
}

// ---------------- EMA update ----------------
__global__ void k_ema(const float* __restrict__ emaw, float* __restrict__ out) {
    int i = blockIdx.x * 256 + threadIdx.x;
    float e = emaw[i] * DECAYF + OMD * g_dw[i];
    out[OFF_EMAW + i] = e;
    out[OFF_W + i]    = e / out[OFF_CS + (i >> 8)];
}

// ---------------- launch ----------------
extern "C" void kernel_launch(void* const* d_in, const int* in_sizes, int n_in,
                              void* d_out, int out_size) {
    const float* z    = (const float*)d_in[0];
    const float* wgt  = (const float*)d_in[1];
    const float* ecs  = (const float*)d_in[2];
    const float* emaw = (const float*)d_in[3];
    float* out = (float*)d_out;

    cudaFuncSetAttribute(k_gemm, cudaFuncAttributeMaxDynamicSharedMemorySize, SMT);

    k_prep_w <<<256, 256>>>(wgt);
    k_gemm   <<<512, 512, SMT>>>(z, out);
    k_resq   <<<1024, 512>>>(wgt, out);
    k_stats  <<<1, 1024>>>(ecs, out);
    k_ema    <<<2048, 256>>>(emaw, out);
}

// round 16
// speedup vs baseline: 1.1303x; 1.0088x over previous
#include <cuda_runtime.h>
#include <cuda_fp16.h>
#include <math.h>
#include <stdint.h>

// ---------------- problem constants ----------------
#define NTOT   65536
#define KCB    2048
#define DIM    256
#define HW     4096
#define DHW    1048576

#define OFF_LOSS 0LL
#define OFF_QOUT 1LL
#define OFF_PERP 16777217LL
#define OFF_ENC  16777218LL
#define OFF_CS   150994946LL
#define OFF_EMAW 150996994LL
#define OFF_W    151521282LL

static const float DECAYF = 0.99f;
static const float OMD    = 0.01f;
static const float EPSF   = 1e-5f;

// ---------------- device scratch ----------------
__device__ __half g_Wh[KCB * DIM];      // code-major fp16 (-2w)   (1MB)
__device__ float  g_Xf[NTOT * DIM];     // token-major fp32 x      (64MB)
__device__ float  g_wnorm[KCB];
__device__ int    g_counts[KCB];
__device__ int4   g_cand4[NTOT];        // 4 exact-rescore candidates per token (1MB)
__device__ float  g_dw[KCB * DIM];
__device__ float  g_loss;               // sum(||x||^2) + sum(min score)

// ---------------- helpers ----------------
__device__ __forceinline__ uint32_t smem_u32(const void* p) {
    uint32_t a;
    asm("{ .reg .u64 t; cvta.to.shared.u64 t, %1; cvt.u32.u64 %0, t; }" : "=r"(a) : "l"(p));
    return a;
}
__device__ __forceinline__ uint32_t h2u(__half2 h) {
    union { __half2 h; uint32_t u; } c; c.h = h; return c.u;
}
__device__ __forceinline__ void cp16(uint32_t dst, const void* src) {
    asm volatile("cp.async.cg.shared.global [%0], [%1], 16;" :: "r"(dst), "l"(src) : "memory");
}
__device__ __forceinline__ void cp_commit() { asm volatile("cp.async.commit_group;" ::: "memory"); }

__device__ __forceinline__ void ldm4(uint32_t a, uint32_t r[4]) {
    asm volatile("ldmatrix.sync.aligned.m8n8.x4.shared.b16 {%0,%1,%2,%3}, [%4];"
                 : "=r"(r[0]), "=r"(r[1]), "=r"(r[2]), "=r"(r[3]) : "r"(a));
}
// fp16-accumulate HMMA
__device__ __forceinline__ void mma16816h(uint32_t c[2], const uint32_t a[4],
                                          uint32_t b0, uint32_t b1) {
    asm volatile("mma.sync.aligned.m16n8k16.row.col.f16.f16.f16.f16 "
                 "{%0,%1},{%2,%3,%4,%5},{%6,%7},{%0,%1};"
                 : "+r"(c[0]), "+r"(c[1])
                 : "r"(a[0]), "r"(a[1]), "r"(a[2]), "r"(a[3]), "r"(b0), "r"(b1));
}

// ---------------- tiny init kernels (also pad launch order so gemm is 4th) ----------------
__global__ void k_init() {
    int i = blockIdx.x * 256 + threadIdx.x;      // 2048
    g_counts[i] = 0;
    if (i == 0) g_loss = 0.0f;
}
__global__ void k_zdw() {
    g_dw[(size_t)blockIdx.x * 256 + threadIdx.x] = 0.0f;   // 2048 blocks
}

// ---------------- codebook prep: fp16(-2w) + norms ----------------
__global__ void k_prep_w(const float* __restrict__ weight) {
    int warp = threadIdx.x >> 5, lane = threadIdx.x & 31;
    int k = blockIdx.x * 8 + warp;               // 256 blocks
    float s = 0.0f;
    #pragma unroll
    for (int i = 0; i < 8; ++i) {
        int d = lane + i * 32;
        float v = weight[(size_t)k * DIM + d];
        g_Wh[(size_t)k * DIM + d] = __float2half(-2.0f * v);
        s += v * v;
    }
    #pragma unroll
    for (int o = 16; o > 0; o >>= 1) s += __shfl_down_sync(0xffffffffu, s, o);
    if (lane == 0) g_wnorm[k] = s;
}

// ---------------- HMMA argmin GEMM + fused x-prep + enc zero-fill ----------------
// 512 CTAs x 512 thr (16 warps: 4m x 4n, warp tile 32x32). CTA = 128 tokens x
// 2048 codes, K=256. Prologue: reads its z slice, writes g_Xf, converts fp16
// into swizzled A tile, accumulates sum(x^2). B double-buffered (2x64KB).
// Enc zero-fill via STG.128 on the +8B-shifted window (2-float head patched by
// CTA0; 2-float tail lands on OFF_CS which k_stats overwrites afterwards).
#define SA  0
#define SB0 65536
#define SB1 131072
#define SMT 196608

__global__ void __launch_bounds__(512, 1)
k_gemm(const float* __restrict__ z, float* __restrict__ out) {
    extern __shared__ char sm[];
    const uint32_t sb = smem_u32(sm);
    const int tid = threadIdx.x;
    const int lane = tid & 31, warp = tid >> 5;
    const int wm = warp & 3, wn = warp >> 2;      // 4m x 4n
    const int n0 = blockIdx.x * 128;
    // 16B-aligned shifted enc window: (OFF_ENC + 2) is 16B aligned
    float4* enc4 = (float4*)(out + OFF_ENC + 2) + (size_t)blockIdx.x * 65536;
    if (blockIdx.x == 0 && tid == 0) {
        out[OFF_ENC] = 0.0f;
        out[OFF_ENC + 1] = 0.0f;
    }

    // ---- fused x prep: z -> staging smem -> (SA fp16 swizzled, g_Xf, sum x^2) ----
    {
        float* xs = (float*)(sm + SB0);           // 64*260 floats staging (66.5KB)
        const int bb = n0 >> 12, sp0 = n0 & 4095;
        const float* zb = z + (size_t)bb * DHW + sp0;
        float la = 0.0f;
        #pragma unroll
        for (int half = 0; half < 2; ++half) {
            const float* zh = zb + half * 64;
            #pragma unroll
            for (int p = 0; p < 8; ++p) {
                int lin = tid + p * 512;          // 4096 = 64 q x 64 dq4
                int q = lin & 63, dq4 = lin >> 6;
                float4 v;
                v.x = zh[(dq4 * 4 + 0) * HW + q];
                v.y = zh[(dq4 * 4 + 1) * HW + q];
                v.z = zh[(dq4 * 4 + 2) * HW + q];
                v.w = zh[(dq4 * 4 + 3) * HW + q];
                *(float4*)(xs + q * 260 + dq4 * 4) = v;
            }
            __syncthreads();
            #pragma unroll
            for (int p = 0; p < 4; ++p) {
                int lin = tid + p * 512;          // 2048 = 64 q x 32 ch
                int q = lin >> 5, ch = lin & 31;
                const float* src = xs + q * 260 + ch * 8;
                float4 f0 = *(const float4*)src;
                float4 f1 = *(const float4*)(src + 4);
                la += f0.x * f0.x + f0.y * f0.y + f0.z * f0.z + f0.w * f0.w
                    + f1.x * f1.x + f1.y * f1.y + f1.z * f1.z + f1.w * f1.w;
                uint4 v;
                v.x = h2u(__floats2half2_rn(f0.x, f0.y));
                v.y = h2u(__floats2half2_rn(f0.z, f0.w));
                v.z = h2u(__floats2half2_rn(f1.x, f1.y));
                v.w = h2u(__floats2half2_rn(f1.z, f1.w));
                int row = half * 64 + q;
                *(uint4*)(sm + SA + row * 512 + ((ch ^ (row & 7)) << 4)) = v;
                float* dst = g_Xf + (size_t)(n0 + row) * DIM + ch * 8;
                *(float4*)dst = f0;
                *(float4*)(dst + 4) = f1;
            }
            __syncthreads();
        }
        #pragma unroll
        for (int o = 16; o > 0; o >>= 1) la += __shfl_xor_sync(0xffffffffu, la, o);
        if (lane == 0) atomicAdd(&g_loss, la);
    }

    // B tile 0
    #pragma unroll
    for (int i = 0; i < 8; ++i) {
        int idx = tid + i * 512;
        int row = idx >> 5, ch = idx & 31;
        cp16(sb + SB0 + row * 512 + ((ch ^ (row & 7)) << 4),
             g_Wh + (size_t)row * DIM + ch * 8);
    }
    cp_commit();
    // B tile 1
    #pragma unroll
    for (int i = 0; i < 8; ++i) {
        int idx = tid + i * 512;
        int row = idx >> 5, ch = idx & 31;
        cp16(sb + SB1 + row * 512 + ((ch ^ (row & 7)) << 4),
             g_Wh + (size_t)(128 + row) * DIM + ch * 8);
    }
    cp_commit();

    // per-thread top-3 for 4 owned token slots (r = mi*2 + h)
    float v1[4], v2[4], v3[4];
    int   i1[4], i2[4], i3[4];
    #pragma unroll
    for (int r = 0; r < 4; ++r) {
        v1[r] = 3.4e38f; v2[r] = 3.4e38f; v3[r] = 3.4e38f;
        i1[r] = 0; i2[r] = 0; i3[r] = 0;
    }

    const float4 zz = make_float4(0.f, 0.f, 0.f, 0.f);

    for (int nt = 0; nt < 16; ++nt) {
        if (nt < 15) asm volatile("cp.async.wait_group 1;" ::: "memory");
        else         asm volatile("cp.async.wait_group 0;" ::: "memory");
        __syncthreads();
        const uint32_t BB = sb + ((nt & 1) ? SB1 : SB0);

        uint32_t c[2][4][2];
        #pragma unroll
        for (int mi = 0; mi < 2; ++mi)
            #pragma unroll
            for (int ni = 0; ni < 4; ++ni) { c[mi][ni][0] = 0u; c[mi][ni][1] = 0u; }

        #pragma unroll
        for (int ks = 0; ks < 16; ++ks) {
            uint32_t a[2][4];
            #pragma unroll
            for (int mi = 0; mi < 2; ++mi) {
                int row = wm * 32 + mi * 16 + (lane & 15);
                int ch = ks * 2 + (lane >> 4);
                ldm4(sb + SA + row * 512 + ((ch ^ (row & 7)) << 4), a[mi]);
            }
            // B: non-trans ldmatrix on code-major smem; two 16-code groups.
            uint32_t b0[4], b1[4];
            {
                int code = wn * 32 + ((lane & 16) >> 1) + (lane & 7);
                int ch = ks * 2 + ((lane >> 3) & 1);
                ldm4(BB + code * 512 + ((ch ^ (code & 7)) << 4), b0);
                code += 16;
                ldm4(BB + code * 512 + ((ch ^ (code & 7)) << 4), b1);
            }
            #pragma unroll
            for (int mi = 0; mi < 2; ++mi) {
                mma16816h(c[mi][0], a[mi], b0[0], b0[1]);
                mma16816h(c[mi][1], a[mi], b0[2], b0[3]);
                mma16816h(c[mi][2], a[mi], b1[0], b1[1]);
                mma16816h(c[mi][3], a[mi], b1[2], b1[3]);
            }
        }

        // zero 8 float4 chunks of this CTA's shifted encodings window (STG.128)
        #pragma unroll
        for (int j = 0; j < 8; ++j)
            __stcs(enc4 + (size_t)(nt * 8 + j) * 512 + tid, zz);

        // fold: score = wnorm + acc  (acc = x . (-2w), fp16 pair); top-3 insert
        #pragma unroll
        for (int ni = 0; ni < 4; ++ni) {
            int col = nt * 128 + wn * 32 + ni * 8 + (lane & 3) * 2;
            float2 wn2 = *(const float2*)&g_wnorm[col];
            #pragma unroll
            for (int mi = 0; mi < 2; ++mi) {
                #pragma unroll
                for (int h = 0; h < 2; ++h) {
                    int r = mi * 2 + h;
                    float2 cf = __half22float2(*(__half2*)&c[mi][ni][h]);
                    float s0 = wn2.x + cf.x;
                    float s1 = wn2.y + cf.y;
                    if (s0 < v3[r]) {
                        if (s0 < v1[r]) { v3[r]=v2[r]; i3[r]=i2[r]; v2[r]=v1[r]; i2[r]=i1[r]; v1[r]=s0; i1[r]=col; }
                        else if (s0 < v2[r]) { v3[r]=v2[r]; i3[r]=i2[r]; v2[r]=s0; i2[r]=col; }
                        else { v3[r]=s0; i3[r]=col; }
                    }
                    if (s1 < v3[r]) {
                        if (s1 < v1[r]) { v3[r]=v2[r]; i3[r]=i2[r]; v2[r]=v1[r]; i2[r]=i1[r]; v1[r]=s1; i1[r]=col+1; }
                        else if (s1 < v2[r]) { v3[r]=v2[r]; i3[r]=i2[r]; v2[r]=s1; i2[r]=col+1; }
                        else { v3[r]=s1; i3[r]=col+1; }
                    }
                }
            }
        }

        __syncthreads();
        if (nt + 2 < 16) {
            const uint32_t NB = sb + ((nt & 1) ? SB1 : SB0);
            #pragma unroll
            for (int i = 0; i < 8; ++i) {
                int idx = tid + i * 512;
                int row = idx >> 5, ch = idx & 31;
                cp16(NB + row * 512 + ((ch ^ (row & 7)) << 4),
                     g_Wh + (size_t)((nt + 2) * 128 + row) * DIM + ch * 8);
            }
            cp_commit();
        }
    }

    // ---- per-token merge: 16 threads x top-3 -> global top-4 (smem, stride 49) ----
    __syncthreads();
    float* cv = (float*)sm;                      // 128 * 49 floats (25088 B)
    int*   ci = (int*)(sm + 25088);              // 128 * 49 ints
    const int slot = wn * 4 + (lane & 3);        // 0..15
    #pragma unroll
    for (int mi = 0; mi < 2; ++mi)
        #pragma unroll
        for (int h = 0; h < 2; ++h) {
            int r = mi * 2 + h;
            int tloc = wm * 32 + mi * 16 + h * 8 + (lane >> 2);
            cv[tloc * 49 + slot * 3 + 0] = v1[r];  ci[tloc * 49 + slot * 3 + 0] = i1[r];
            cv[tloc * 49 + slot * 3 + 1] = v2[r];  ci[tloc * 49 + slot * 3 + 1] = i2[r];
            cv[tloc * 49 + slot * 3 + 2] = v3[r];  ci[tloc * 49 + slot * 3 + 2] = i3[r];
        }
    __syncthreads();
    if (tid < 128) {
        float bv0 = 3.4e38f, bv1b = 3.4e38f, bv2b = 3.4e38f, bv3 = 3.4e38f;
        int   bx0 = 0, bx1 = 0, bx2 = 0, bx3 = 0;
        #pragma unroll
        for (int e = 0; e < 48; ++e) {
            float v = cv[tid * 49 + e];
            int   ix = ci[tid * 49 + e];
            if (v < bv3) {
                if (v < bv0) { bv3=bv2b; bx3=bx2; bv2b=bv1b; bx2=bx1; bv1b=bv0; bx1=bx0; bv0=v; bx0=ix; }
                else if (v < bv1b) { bv3=bv2b; bx3=bx2; bv2b=bv1b; bx2=bx1; bv1b=v; bx1=ix; }
                else if (v < bv2b) { bv3=bv2b; bx3=bx2; bv2b=v; bx2=ix; }
                else { bv3=v; bx3=ix; }
            }
        }
        g_cand4[n0 + tid] = make_int4(bx0, bx1, bx2, bx3);
    }
}

// ---------------- fused: exact rescore + loss + dw + encodings + q_out ----------------
// 1024 blocks (one per 64-token row) x 512 thr. Warp w owns tokens w*4..w*4+3.
__global__ void __launch_bounds__(512)
k_resq(const float* __restrict__ weight, float* __restrict__ out) {
    __shared__ float wrow[64 * 67];
    __shared__ int   idx_s[64];
    __shared__ float ls[16];
    const int tid = threadIdx.x;
    const int warp = tid >> 5, lane = tid & 31;
    const int blk = blockIdx.x;
    const int b = blk >> 6, h = blk & 63;
    const int n0 = b * HW + h * 64;

    float lacc = 0.0f;
    #pragma unroll
    for (int it = 0; it < 4; ++it) {
        int tok = n0 + warp * 4 + it;
        int4 cc = g_cand4[tok];
        const float* w0 = weight + (size_t)cc.x * DIM + lane;
        const float* w1 = weight + (size_t)cc.y * DIM + lane;
        const float* w2 = weight + (size_t)cc.z * DIM + lane;
        const float* w3 = weight + (size_t)cc.w * DIM + lane;
        float xv[8];
        float d0 = 0.0f, d1 = 0.0f, d2 = 0.0f, d3 = 0.0f;
        #pragma unroll
        for (int i = 0; i < 8; ++i)
            xv[i] = g_Xf[(size_t)tok * DIM + lane + 32 * i];
        #pragma unroll
        for (int i = 0; i < 8; ++i) {
            float a0 = __ldg(w0 + 32 * i);
            float a1 = __ldg(w1 + 32 * i);
            float a2 = __ldg(w2 + 32 * i);
            float a3 = __ldg(w3 + 32 * i);
            d0 += xv[i] * a0;
            d1 += xv[i] * a1;
            d2 += xv[i] * a2;
            d3 += xv[i] * a3;
        }
        #pragma unroll
        for (int o = 16; o > 0; o >>= 1) {
            d0 += __shfl_xor_sync(0xffffffffu, d0, o);
            d1 += __shfl_xor_sync(0xffffffffu, d1, o);
            d2 += __shfl_xor_sync(0xffffffffu, d2, o);
            d3 += __shfl_xor_sync(0xffffffffu, d3, o);
        }
        float s0 = g_wnorm[cc.x] - 2.0f * d0;
        float s1 = g_wnorm[cc.y] - 2.0f * d1;
        float s2 = g_wnorm[cc.z] - 2.0f * d2;
        float s3 = g_wnorm[cc.w] - 2.0f * d3;
        float bs = s0; int bi = cc.x;
        if (s1 < bs || (s1 == bs && cc.y < bi)) { bs = s1; bi = cc.y; }
        if (s2 < bs || (s2 == bs && cc.z < bi)) { bs = s2; bi = cc.z; }
        if (s3 < bs || (s3 == bs && cc.w < bi)) { bs = s3; bi = cc.w; }
        // dw accumulation (coalesced REDs)
        float* dwr = g_dw + (size_t)bi * DIM + lane;
        #pragma unroll
        for (int i = 0; i < 8; ++i)
            atomicAdd(dwr + 32 * i, xv[i]);
        if (lane == 0) {
            idx_s[warp * 4 + it] = bi;
            atomicAdd(&g_counts[bi], 1);
            out[OFF_ENC + (long long)tok * KCB + bi] = 1.0f;
            lacc += bs;               // ||x||^2 part added in gemm prologue
        }
    }
    if (lane == 0) ls[warp] = lacc;
    __syncthreads();
    if (tid == 0) {
        float s = 0.0f;
        #pragma unroll
        for (int w = 0; w < 16; ++w) s += ls[w];
        atomicAdd(&g_loss, s);
    }

    // ---- quant phase: stage gathered rows, write q_out coalesced ----
    const int w = tid & 63, dg = tid >> 6;       // dg 0..7
    float* qbp = out + OFF_QOUT + (size_t)b * DHW + h * 64 + w;
    for (int c = 0; c < 4; ++c) {
        #pragma unroll
        for (int p = 0; p < 8; ++p) {
            int idx = tid + p * 512;
            int r = idx >> 6, d = idx & 63;
            wrow[r * 67 + d] = __ldg(weight + (size_t)idx_s[r] * DIM + c * 64 + d);
        }
        __syncthreads();
        #pragma unroll
        for (int s = 0; s < 8; ++s) {
            int dl = dg * 8 + s;
            int d = c * 64 + dl;
            __stcs(qbp + (size_t)d * HW, wrow[w * 67 + dl]);
        }
        __syncthreads();
    }
}

// ---------------- stats ----------------
__global__ void k_stats(const float* __restrict__ ecs, float* __restrict__ out) {
    __shared__ float sn[1024];
    __shared__ float sh[1024];
    int t = threadIdx.x;
    float c0 = (float)g_counts[t];
    float c1 = (float)g_counts[t + 1024];
    float cs0 = ecs[t] * DECAYF + OMD * c0;
    float cs1 = ecs[t + 1024] * DECAYF + OMD * c1;
    float p0 = c0 / 65536.0f, p1 = c1 / 65536.0f;
    sn[t] = cs0 + cs1;
    sh[t] = p0 * logf(p0 + 1e-10f) + p1 * logf(p1 + 1e-10f);
    __syncthreads();
    #pragma unroll
    for (int st = 512; st > 0; st >>= 1) {
        if (t < st) { sn[t] += sn[t + st]; sh[t] += sh[t + st]; }
        __syncthreads();
    }
    float n = sn[0];
    float denom = n + (float)KCB * EPSF;
    out[OFF_CS + t]        = (cs0 + EPSF) / denom * n;
    out[OFF_CS + t + 1024] = (cs1 + EPSF) / denom * n;
    if (t == 0) {
        out[OFF_PERP] = expf(-sh[0]);
        out[OFF_LOSS] = 0.25f * g_loss / 16777216.0f;
    }
}

// ---------------- EMA update ----------------
__global__ void k_ema(const float* __restrict__ emaw, float* __restrict__ out) {
    int i = blockIdx.x * 256 + threadIdx.x;
    float e = emaw[i] * DECAYF + OMD * g_dw[i];
    out[OFF_EMAW + i] = e;
    out[OFF_W + i]    = e / out[OFF_CS + (i >> 8)];
}

// ---------------- launch ----------------
extern "C" void kernel_launch(void* const* d_in, const int* in_sizes, int n_in,
                              void* d_out, int out_size) {
    const float* z    = (const float*)d_in[0];
    const float* wgt  = (const float*)d_in[1];
    const float* ecs  = (const float*)d_in[2];
    const float* emaw = (const float*)d_in[3];
    float* out = (float*)d_out;

    cudaFuncSetAttribute(k_gemm, cudaFuncAttributeMaxDynamicSharedMemorySize, SMT);

    k_init   <<<8, 256>>>();          // 1
    k_zdw    <<<2048, 256>>>();       // 2
    k_prep_w <<<256, 256>>>(wgt);     // 3
    k_gemm   <<<512, 512, SMT>>>(z, out);   // 4  <- profiled slot
    k_resq   <<<1024, 512>>>(wgt, out);
    k_stats  <<<1, 1024>>>(ecs, out);
    k_ema    <<<2048, 256>>>(emaw, out);
}

// round 17
// speedup vs baseline: 1.1310x; 1.0006x over previous
#include <cuda_runtime.h>
#include <cuda_fp16.h>
#include <math.h>
#include <stdint.h>

// ---------------- problem constants ----------------
#define NTOT   65536
#define KCB    2048
#define DIM    256
#define HW     4096
#define DHW    1048576

#define OFF_LOSS 0LL
#define OFF_QOUT 1LL
#define OFF_PERP 16777217LL
#define OFF_ENC  16777218LL
#define OFF_CS   150994946LL
#define OFF_EMAW 150996994LL
#define OFF_W    151521282LL

static const float DECAYF = 0.99f;
static const float OMD    = 0.01f;
static const float EPSF   = 1e-5f;

// ---------------- device scratch ----------------
__device__ __half g_Wh[KCB * DIM];      // code-major fp16 (-2w)   (1MB)
__device__ float  g_Xf[NTOT * DIM];     // token-major fp32 x      (64MB)
__device__ float  g_wnorm[KCB];
__device__ int    g_counts[KCB];
__device__ int4   g_cand4[NTOT];        // 4 exact-rescore candidates per token (1MB)
__device__ float  g_dw[KCB * DIM];
__device__ float  g_loss;               // sum(||x||^2) + sum(min score)

// ---------------- helpers ----------------
__device__ __forceinline__ uint32_t smem_u32(const void* p) {
    uint32_t a;
    asm("{ .reg .u64 t; cvta.to.shared.u64 t, %1; cvt.u32.u64 %0, t; }" : "=r"(a) : "l"(p));
    return a;
}
__device__ __forceinline__ uint32_t h2u(__half2 h) {
    union { __half2 h; uint32_t u; } c; c.h = h; return c.u;
}
__device__ __forceinline__ void cp16(uint32_t dst, const void* src) {
    asm volatile("cp.async.cg.shared.global [%0], [%1], 16;" :: "r"(dst), "l"(src) : "memory");
}
__device__ __forceinline__ void cp_commit() { asm volatile("cp.async.commit_group;" ::: "memory"); }

// NON-volatile ldmatrix: "memory" keeps it ordered vs barriers/stores, but the
// scheduler may interleave it with (register-only) MMAs for software pipelining.
__device__ __forceinline__ void ldm4(uint32_t a, uint32_t r[4]) {
    asm("ldmatrix.sync.aligned.m8n8.x4.shared.b16 {%0,%1,%2,%3}, [%4];"
        : "=r"(r[0]), "=r"(r[1]), "=r"(r[2]), "=r"(r[3]) : "r"(a) : "memory");
}
// NON-volatile fp16-accumulate HMMA: pure register op, dependencies order it.
__device__ __forceinline__ void mma16816h(uint32_t c[2], const uint32_t a[4],
                                          uint32_t b0, uint32_t b1) {
    asm("mma.sync.aligned.m16n8k16.row.col.f16.f16.f16.f16 "
        "{%0,%1},{%2,%3,%4,%5},{%6,%7},{%0,%1};"
        : "+r"(c[0]), "+r"(c[1])
        : "r"(a[0]), "r"(a[1]), "r"(a[2]), "r"(a[3]), "r"(b0), "r"(b1));
}

// ---------------- tiny init kernels (keep gemm as the 4th launch) ----------------
__global__ void k_init() {
    int i = blockIdx.x * 256 + threadIdx.x;      // 2048
    g_counts[i] = 0;
    if (i == 0) g_loss = 0.0f;
}
__global__ void k_zdw() {
    g_dw[(size_t)blockIdx.x * 256 + threadIdx.x] = 0.0f;   // 2048 blocks
}

// ---------------- codebook prep: fp16(-2w) + norms ----------------
__global__ void k_prep_w(const float* __restrict__ weight) {
    int warp = threadIdx.x >> 5, lane = threadIdx.x & 31;
    int k = blockIdx.x * 8 + warp;               // 256 blocks
    float s = 0.0f;
    #pragma unroll
    for (int i = 0; i < 8; ++i) {
        int d = lane + i * 32;
        float v = weight[(size_t)k * DIM + d];
        g_Wh[(size_t)k * DIM + d] = __float2half(-2.0f * v);
        s += v * v;
    }
    #pragma unroll
    for (int o = 16; o > 0; o >>= 1) s += __shfl_down_sync(0xffffffffu, s, o);
    if (lane == 0) g_wnorm[k] = s;
}

// ---------------- HMMA argmin GEMM + fused x-prep + enc zero-fill ----------------
// 512 CTAs x 512 thr (16 warps: 4m x 4n, warp tile 32x32). CTA = 128 tokens x
// 2048 codes, K=256. Prologue: reads its z slice, writes g_Xf, converts fp16
// into swizzled A tile, accumulates sum(x^2). B double-buffered (2x64KB).
#define SA  0
#define SB0 65536
#define SB1 131072
#define SMT 196608

__global__ void __launch_bounds__(512, 1)
k_gemm(const float* __restrict__ z, float* __restrict__ out) {
    extern __shared__ char sm[];
    const uint32_t sb = smem_u32(sm);
    const int tid = threadIdx.x;
    const int lane = tid & 31, warp = tid >> 5;
    const int wm = warp & 3, wn = warp >> 2;      // 4m x 4n
    const int n0 = blockIdx.x * 128;
    // 16B-aligned shifted enc window: (OFF_ENC + 2) is 16B aligned
    float4* enc4 = (float4*)(out + OFF_ENC + 2) + (size_t)blockIdx.x * 65536;
    if (blockIdx.x == 0 && tid == 0) {
        out[OFF_ENC] = 0.0f;
        out[OFF_ENC + 1] = 0.0f;
    }

    // ---- fused x prep: z -> staging smem -> (SA fp16 swizzled, g_Xf, sum x^2) ----
    {
        float* xs = (float*)(sm + SB0);           // 64*260 floats staging (66.5KB)
        const int bb = n0 >> 12, sp0 = n0 & 4095;
        const float* zb = z + (size_t)bb * DHW + sp0;
        float la = 0.0f;
        #pragma unroll
        for (int half = 0; half < 2; ++half) {
            const float* zh = zb + half * 64;
            #pragma unroll
            for (int p = 0; p < 8; ++p) {
                int lin = tid + p * 512;          // 4096 = 64 q x 64 dq4
                int q = lin & 63, dq4 = lin >> 6;
                float4 v;
                v.x = zh[(dq4 * 4 + 0) * HW + q];
                v.y = zh[(dq4 * 4 + 1) * HW + q];
                v.z = zh[(dq4 * 4 + 2) * HW + q];
                v.w = zh[(dq4 * 4 + 3) * HW + q];
                *(float4*)(xs + q * 260 + dq4 * 4) = v;
            }
            __syncthreads();
            #pragma unroll
            for (int p = 0; p < 4; ++p) {
                int lin = tid + p * 512;          // 2048 = 64 q x 32 ch
                int q = lin >> 5, ch = lin & 31;
                const float* src = xs + q * 260 + ch * 8;
                float4 f0 = *(const float4*)src;
                float4 f1 = *(const float4*)(src + 4);
                la += f0.x * f0.x + f0.y * f0.y + f0.z * f0.z + f0.w * f0.w
                    + f1.x * f1.x + f1.y * f1.y + f1.z * f1.z + f1.w * f1.w;
                uint4 v;
                v.x = h2u(__floats2half2_rn(f0.x, f0.y));
                v.y = h2u(__floats2half2_rn(f0.z, f0.w));
                v.z = h2u(__floats2half2_rn(f1.x, f1.y));
                v.w = h2u(__floats2half2_rn(f1.z, f1.w));
                int row = half * 64 + q;
                *(uint4*)(sm + SA + row * 512 + ((ch ^ (row & 7)) << 4)) = v;
                float* dst = g_Xf + (size_t)(n0 + row) * DIM + ch * 8;
                *(float4*)dst = f0;
                *(float4*)(dst + 4) = f1;
            }
            __syncthreads();
        }
        #pragma unroll
        for (int o = 16; o > 0; o >>= 1) la += __shfl_xor_sync(0xffffffffu, la, o);
        if (lane == 0) atomicAdd(&g_loss, la);
    }

    // B tile 0
    #pragma unroll
    for (int i = 0; i < 8; ++i) {
        int idx = tid + i * 512;
        int row = idx >> 5, ch = idx & 31;
        cp16(sb + SB0 + row * 512 + ((ch ^ (row & 7)) << 4),
             g_Wh + (size_t)row * DIM + ch * 8);
    }
    cp_commit();
    // B tile 1
    #pragma unroll
    for (int i = 0; i < 8; ++i) {
        int idx = tid + i * 512;
        int row = idx >> 5, ch = idx & 31;
        cp16(sb + SB1 + row * 512 + ((ch ^ (row & 7)) << 4),
             g_Wh + (size_t)(128 + row) * DIM + ch * 8);
    }
    cp_commit();

    // per-thread top-3 for 4 owned token slots (r = mi*2 + h)
    float v1[4], v2[4], v3[4];
    int   i1[4], i2[4], i3[4];
    #pragma unroll
    for (int r = 0; r < 4; ++r) {
        v1[r] = 3.4e38f; v2[r] = 3.4e38f; v3[r] = 3.4e38f;
        i1[r] = 0; i2[r] = 0; i3[r] = 0;
    }

    const float4 zz = make_float4(0.f, 0.f, 0.f, 0.f);

    for (int nt = 0; nt < 16; ++nt) {
        if (nt < 15) asm volatile("cp.async.wait_group 1;" ::: "memory");
        else         asm volatile("cp.async.wait_group 0;" ::: "memory");
        __syncthreads();
        const uint32_t BB = sb + ((nt & 1) ? SB1 : SB0);

        uint32_t c[2][4][2];
        #pragma unroll
        for (int mi = 0; mi < 2; ++mi)
            #pragma unroll
            for (int ni = 0; ni < 4; ++ni) { c[mi][ni][0] = 0u; c[mi][ni][1] = 0u; }

        #pragma unroll
        for (int ks = 0; ks < 16; ++ks) {
            uint32_t a[2][4];
            #pragma unroll
            for (int mi = 0; mi < 2; ++mi) {
                int row = wm * 32 + mi * 16 + (lane & 15);
                int ch = ks * 2 + (lane >> 4);
                ldm4(sb + SA + row * 512 + ((ch ^ (row & 7)) << 4), a[mi]);
            }
            // B: non-trans ldmatrix on code-major smem; two 16-code groups.
            uint32_t b0[4], b1[4];
            {
                int code = wn * 32 + ((lane & 16) >> 1) + (lane & 7);
                int ch = ks * 2 + ((lane >> 3) & 1);
                ldm4(BB + code * 512 + ((ch ^ (code & 7)) << 4), b0);
                code += 16;
                ldm4(BB + code * 512 + ((ch ^ (code & 7)) << 4), b1);
            }
            #pragma unroll
            for (int mi = 0; mi < 2; ++mi) {
                mma16816h(c[mi][0], a[mi], b0[0], b0[1]);
                mma16816h(c[mi][1], a[mi], b0[2], b0[3]);
                mma16816h(c[mi][2], a[mi], b1[0], b1[1]);
                mma16816h(c[mi][3], a[mi], b1[2], b1[3]);
            }
        }

        // zero 8 float4 chunks of this CTA's shifted encodings window (STG.128)
        #pragma unroll
        for (int j = 0; j < 8; ++j)
            __stcs(enc4 + (size_t)(nt * 8 + j) * 512 + tid, zz);

        // fold: score = wnorm + acc  (acc = x . (-2w), fp16 pair); top-3 insert
        #pragma unroll
        for (int ni = 0; ni < 4; ++ni) {
            int col = nt * 128 + wn * 32 + ni * 8 + (lane & 3) * 2;
            float2 wn2 = *(const float2*)&g_wnorm[col];
            #pragma unroll
            for (int mi = 0; mi < 2; ++mi) {
                #pragma unroll
                for (int h = 0; h < 2; ++h) {
                    int r = mi * 2 + h;
                    float2 cf = __half22float2(*(__half2*)&c[mi][ni][h]);
                    float s0 = wn2.x + cf.x;
                    float s1 = wn2.y + cf.y;
                    if (s0 < v3[r]) {
                        if (s0 < v1[r]) { v3[r]=v2[r]; i3[r]=i2[r]; v2[r]=v1[r]; i2[r]=i1[r]; v1[r]=s0; i1[r]=col; }
                        else if (s0 < v2[r]) { v3[r]=v2[r]; i3[r]=i2[r]; v2[r]=s0; i2[r]=col; }
                        else { v3[r]=s0; i3[r]=col; }
                    }
                    if (s1 < v3[r]) {
                        if (s1 < v1[r]) { v3[r]=v2[r]; i3[r]=i2[r]; v2[r]=v1[r]; i2[r]=i1[r]; v1[r]=s1; i1[r]=col+1; }
                        else if (s1 < v2[r]) { v3[r]=v2[r]; i3[r]=i2[r]; v2[r]=s1; i2[r]=col+1; }
                        else { v3[r]=s1; i3[r]=col+1; }
                    }
                }
            }
        }

        __syncthreads();
        if (nt + 2 < 16) {
            const uint32_t NB = sb + ((nt & 1) ? SB1 : SB0);
            #pragma unroll
            for (int i = 0; i < 8; ++i) {
                int idx = tid + i * 512;
                int row = idx >> 5, ch = idx & 31;
                cp16(NB + row * 512 + ((ch ^ (row & 7)) << 4),
                     g_Wh + (size_t)((nt + 2) * 128 + row) * DIM + ch * 8);
            }
            cp_commit();
        }
    }

    // ---- per-token merge: 16 threads x top-3 -> global top-4 (smem, stride 49) ----
    __syncthreads();
    float* cv = (float*)sm;                      // 128 * 49 floats (25088 B)
    int*   ci = (int*)(sm + 25088);              // 128 * 49 ints
    const int slot = wn * 4 + (lane & 3);        // 0..15
    #pragma unroll
    for (int mi = 0; mi < 2; ++mi)
        #pragma unroll
        for (int h = 0; h < 2; ++h) {
            int r = mi * 2 + h;
            int tloc = wm * 32 + mi * 16 + h * 8 + (lane >> 2);
            cv[tloc * 49 + slot * 3 + 0] = v1[r];  ci[tloc * 49 + slot * 3 + 0] = i1[r];
            cv[tloc * 49 + slot * 3 + 1] = v2[r];  ci[tloc * 49 + slot * 3 + 1] = i2[r];
            cv[tloc * 49 + slot * 3 + 2] = v3[r];  ci[tloc * 49 + slot * 3 + 2] = i3[r];
        }
    __syncthreads();
    if (tid < 128) {
        float bv0 = 3.4e38f, bv1b = 3.4e38f, bv2b = 3.4e38f, bv3 = 3.4e38f;
        int   bx0 = 0, bx1 = 0, bx2 = 0, bx3 = 0;
        #pragma unroll
        for (int e = 0; e < 48; ++e) {
            float v = cv[tid * 49 + e];
            int   ix = ci[tid * 49 + e];
            if (v < bv3) {
                if (v < bv0) { bv3=bv2b; bx3=bx2; bv2b=bv1b; bx2=bx1; bv1b=bv0; bx1=bx0; bv0=v; bx0=ix; }
                else if (v < bv1b) { bv3=bv2b; bx3=bx2; bv2b=bv1b; bx2=bx1; bv1b=v; bx1=ix; }
                else if (v < bv2b) { bv3=bv2b; bx3=bx2; bv2b=v; bx2=ix; }
                else { bv3=v; bx3=ix; }
            }
        }
        g_cand4[n0 + tid] = make_int4(bx0, bx1, bx2, bx3);
    }
}

// ---------------- fused: exact rescore + loss + dw + encodings + q_out ----------------
// 1024 blocks (one per 64-token row) x 512 thr. Warp w owns tokens w*4..w*4+3.
__global__ void __launch_bounds__(512)
k_resq(const float* __restrict__ weight, float* __restrict__ out) {
    __shared__ float wrow[64 * 67];
    __shared__ int   idx_s[64];
    __shared__ float ls[16];
    const int tid = threadIdx.x;
    const int warp = tid >> 5, lane = tid & 31;
    const int blk = blockIdx.x;
    const int b = blk >> 6, h = blk & 63;
    const int n0 = b * HW + h * 64;

    float lacc = 0.0f;
    #pragma unroll
    for (int it = 0; it < 4; ++it) {
        int tok = n0 + warp * 4 + it;
        int4 cc = g_cand4[tok];
        const float* w0 = weight + (size_t)cc.x * DIM + lane;
        const float* w1 = weight + (size_t)cc.y * DIM + lane;
        const float* w2 = weight + (size_t)cc.z * DIM + lane;
        const float* w3 = weight + (size_t)cc.w * DIM + lane;
        float xv[8];
        float d0 = 0.0f, d1 = 0.0f, d2 = 0.0f, d3 = 0.0f;
        #pragma unroll
        for (int i = 0; i < 8; ++i)
            xv[i] = g_Xf[(size_t)tok * DIM + lane + 32 * i];
        #pragma unroll
        for (int i = 0; i < 8; ++i) {
            float a0 = __ldg(w0 + 32 * i);
            float a1 = __ldg(w1 + 32 * i);
            float a2 = __ldg(w2 + 32 * i);
            float a3 = __ldg(w3 + 32 * i);
            d0 += xv[i] * a0;
            d1 += xv[i] * a1;
            d2 += xv[i] * a2;
            d3 += xv[i] * a3;
        }
        #pragma unroll
        for (int o = 16; o > 0; o >>= 1) {
            d0 += __shfl_xor_sync(0xffffffffu, d0, o);
            d1 += __shfl_xor_sync(0xffffffffu, d1, o);
            d2 += __shfl_xor_sync(0xffffffffu, d2, o);
            d3 += __shfl_xor_sync(0xffffffffu, d3, o);
        }
        float s0 = g_wnorm[cc.x] - 2.0f * d0;
        float s1 = g_wnorm[cc.y] - 2.0f * d1;
        float s2 = g_wnorm[cc.z] - 2.0f * d2;
        float s3 = g_wnorm[cc.w] - 2.0f * d3;
        float bs = s0; int bi = cc.x;
        if (s1 < bs || (s1 == bs && cc.y < bi)) { bs = s1; bi = cc.y; }
        if (s2 < bs || (s2 == bs && cc.z < bi)) { bs = s2; bi = cc.z; }
        if (s3 < bs || (s3 == bs && cc.w < bi)) { bs = s3; bi = cc.w; }
        // dw accumulation (coalesced REDs)
        float* dwr = g_dw + (size_t)bi * DIM + lane;
        #pragma unroll
        for (int i = 0; i < 8; ++i)
            atomicAdd(dwr + 32 * i, xv[i]);
        if (lane == 0) {
            idx_s[warp * 4 + it] = bi;
            atomicAdd(&g_counts[bi], 1);
            out[OFF_ENC + (long long)tok * KCB + bi] = 1.0f;
            lacc += bs;               // ||x||^2 part added in gemm prologue
        }
    }
    if (lane == 0) ls[warp] = lacc;
    __syncthreads();
    if (tid == 0) {
        float s = 0.0f;
        #pragma unroll
        for (int w = 0; w < 16; ++w) s += ls[w];
        atomicAdd(&g_loss, s);
    }

    // ---- quant phase: stage gathered rows, write q_out coalesced ----
    const int w = tid & 63, dg = tid >> 6;       // dg 0..7
    float* qbp = out + OFF_QOUT + (size_t)b * DHW + h * 64 + w;
    for (int c = 0; c < 4; ++c) {
        #pragma unroll
        for (int p = 0; p < 8; ++p) {
            int idx = tid + p * 512;
            int r = idx >> 6, d = idx & 63;
            wrow[r * 67 + d] = __ldg(weight + (size_t)idx_s[r] * DIM + c * 64 + d);
        }
        __syncthreads();
        #pragma unroll
        for (int s = 0; s < 8; ++s) {
            int dl = dg * 8 + s;
            int d = c * 64 + dl;
            __stcs(qbp + (size_t)d * HW, wrow[w * 67 + dl]);
        }
        __syncthreads();
    }
}

// ---------------- stats ----------------
__global__ void k_stats(const float* __restrict__ ecs, float* __restrict__ out) {
    __shared__ float sn[1024];
    __shared__ float sh[1024];
    int t = threadIdx.x;
    float c0 = (float)g_counts[t];
    float c1 = (float)g_counts[t + 1024];
    float cs0 = ecs[t] * DECAYF + OMD * c0;
    float cs1 = ecs[t + 1024] * DECAYF + OMD * c1;
    float p0 = c0 / 65536.0f, p1 = c1 / 65536.0f;
    sn[t] = cs0 + cs1;
    sh[t] = p0 * logf(p0 + 1e-10f) + p1 * logf(p1 + 1e-10f);
    __syncthreads();
    #pragma unroll
    for (int st = 512; st > 0; st >>= 1) {
        if (t < st) { sn[t] += sn[t + st]; sh[t] += sh[t + st]; }
        __syncthreads();
    }
    float n = sn[0];
    float denom = n + (float)KCB * EPSF;
    out[OFF_CS + t]        = (cs0 + EPSF) / denom * n;
    out[OFF_CS + t + 1024] = (cs1 + EPSF) / denom * n;
    if (t == 0) {
        out[OFF_PERP] = expf(-sh[0]);
        out[OFF_LOSS] = 0.25f * g_loss / 16777216.0f;
    }
}

// ---------------- EMA update ----------------
__global__ void k_ema(const float* __restrict__ emaw, float* __restrict__ out) {
    int i = blockIdx.x * 256 + threadIdx.x;
    float e = emaw[i] * DECAYF + OMD * g_dw[i];
    out[OFF_EMAW + i] = e;
    out[OFF_W + i]    = e / out[OFF_CS + (i >> 8)];
}

// ---------------- launch ----------------
extern "C" void kernel_launch(void* const* d_in, const int* in_sizes, int n_in,
                              void* d_out, int out_size) {
    const float* z    = (const float*)d_in[0];
    const float* wgt  = (const float*)d_in[1];
    const float* ecs  = (const float*)d_in[2];
    const float* emaw = (const float*)d_in[3];
    float* out = (float*)d_out;

    cudaFuncSetAttribute(k_gemm, cudaFuncAttributeMaxDynamicSharedMemorySize, SMT);

    k_init   <<<8, 256>>>();          // 1
    k_zdw    <<<2048, 256>>>();       // 2
    k_prep_w <<<256, 256>>>(wgt);     // 3
    k_gemm   <<<512, 512, SMT>>>(z, out);   // 4  <- profiled slot
    k_resq   <<<1024, 512>>>(wgt, out);
    k_stats  <<<1, 1024>>>(ecs, out);
    k_ema    <<<2048, 256>>>(emaw, out);
}